// round 7
// baseline (speedup 1.0000x reference)
#include <cuda_runtime.h>
#include <cuda_bf16.h>
#include <stdint.h>

#define N_ENTS 50000
#define N_RELS 500
#define N_TOT  50500
#define EMB    256
#define N_EDGES 400000
#define BATCH  512
#define BN_EPS 1e-5f
#define KS2    512   // h|l storage width (bf16x3 streams 768 via chunk tables)

// ---------------- scratch (__device__ globals, no allocations) ----------------
__device__ float g_XR[(size_t)N_TOT * EMB];
__device__ float g_sup[(size_t)N_TOT * EMB];
__device__ float g_agg[(size_t)N_TOT * EMB];
__device__ float g_XRrf[(size_t)N_TOT * EMB];
__device__ float g_hr[(size_t)BATCH * EMB];
__device__ float g_HamT[EMB * EMB];
__device__ float g_H1T[EMB * EMB];
__device__ float g_H2T[EMB * EMB];
__device__ float g_csum[EMB];
__device__ float g_csq[EMB];
__device__ float g_scale[EMB];
__device__ float g_shift[EMB];

// h|l split buffers: [n, 512] bf16, cols 0-255 = hi, 256-511 = lo
__device__ __nv_bfloat16 g_SA1[(size_t)N_TOT * KS2];     // split of XR (A and score-B)
__device__ __nv_bfloat16 g_SA2[(size_t)N_TOT * KS2];     // split of XRrf
__device__ __nv_bfloat16 g_SA3[(size_t)N_ENTS * KS2];    // split of Xef
__device__ __nv_bfloat16 g_Wb[EMB * KS2];                // split weights
__device__ __nv_bfloat16 g_hrA[(size_t)BATCH * KS2];     // split hr

// quaternion block tables
__constant__ int   c_comp[4][4] = {{0,1,2,3},{1,0,3,2},{2,3,0,1},{3,2,1,0}};
__constant__ float c_sign[4][4] = {{ 1.f, 1.f, 1.f, 1.f},
                                   {-1.f, 1.f, 1.f,-1.f},
                                   {-1.f,-1.f, 1.f, 1.f},
                                   {-1.f, 1.f,-1.f, 1.f}};

// bf16x3 chunk schedule (64-half chunks): AhBh x4, AlBh x4, AhBl x4
__constant__ int c_ka[12] = {0,64,128,192, 256,320,384,448, 0,64,128,192};
__constant__ int c_kb[12] = {0,64,128,192, 0,64,128,192, 256,320,384,448};

// ---------------- helpers ----------------
static __device__ __forceinline__ void split1(float x, __nv_bfloat16& h, __nv_bfloat16& l) {
    h = __float2bfloat16(x);
    l = __float2bfloat16(x - __bfloat162float(h));
}
static __device__ __forceinline__ uint2 pack4(__nv_bfloat16 a, __nv_bfloat16 b,
                                              __nv_bfloat16 c, __nv_bfloat16 d) {
    uint2 u;
    u.x = ((uint32_t)__bfloat16_as_ushort(b) << 16) | __bfloat16_as_ushort(a);
    u.y = ((uint32_t)__bfloat16_as_ushort(d) << 16) | __bfloat16_as_ushort(c);
    return u;
}

// ---------------- hamilton builders (store TRANSPOSED: HT[c*K + k]) ----------------
__global__ void build_hamT(const float* __restrict__ W, float* __restrict__ HT) {
    int idx = blockIdx.x * blockDim.x + threadIdx.x;
    if (idx >= EMB * EMB) return;
    int c = idx >> 8, k = idx & 255;
    int a = k >> 6, u = k & 63, b = c >> 6, v = c & 63;
    HT[idx] = c_sign[a][b] * W[u * EMB + c_comp[a][b] * 64 + v];
}

__global__ void build_hamLPT(const float* __restrict__ W, float* __restrict__ H1,
                             float* __restrict__ H2) {
    int c = blockIdx.x, j = threadIdx.x;
    int q = j >> 6, s = j & 63;
    int b = c >> 6, v = c & 63;
    int pe = 128 * q + s;
    int pr = pe + 64;
    int a1 = pe >> 7, u1 = pe & 127;
    int a2 = pr >> 7, u2 = pr & 127;
    H1[c * EMB + j] = c_sign[a1][b] * W[u1 * EMB + c_comp[a1][b] * 64 + v];
    H2[c * EMB + j] = c_sign[a2][b] * W[u2 * EMB + c_comp[a2][b] * 64 + v];
}

// ---------------- h|l split conversion ----------------
__global__ void split_hl(const float* __restrict__ in, __nv_bfloat16* __restrict__ out,
                         int n64) {
    int i = blockIdx.x * blockDim.x + threadIdx.x;
    if (i >= n64) return;
    int r = i >> 6, c4 = (i & 63) << 2;
    float4 x = *(const float4*)(in + (size_t)r * EMB + c4);
    __nv_bfloat16 h[4], l[4];
    split1(x.x, h[0], l[0]); split1(x.y, h[1], l[1]);
    split1(x.z, h[2], l[2]); split1(x.w, h[3], l[3]);
    size_t b = (size_t)r * KS2 + c4;
    *(uint2*)(out + b) = pack4(h[0], h[1], h[2], h[3]);
    *(uint2*)(out + b + 256) = pack4(l[0], l[1], l[2], l[3]);
}

// bn+tanh fused with h|l split output; optional float output
template <bool WF>
__global__ void bn_tanh_split(const float* __restrict__ X, float* __restrict__ Y,
                              __nv_bfloat16* __restrict__ out, int n64) {
    int i = blockIdx.x * blockDim.x + threadIdx.x;
    if (i >= n64) return;
    int r = i >> 6, c4 = (i & 63) << 2;
    float4 x = *(const float4*)(X + (size_t)r * EMB + c4);
    float y[4];
    float* xs = &x.x;
#pragma unroll
    for (int j = 0; j < 4; j++) {
        float z = xs[j] * g_scale[c4 + j] + g_shift[c4 + j];
        float e = __expf(-2.f * fabsf(z));
        float t = (1.f - e) / (1.f + e);
        y[j] = copysignf(t, z);
    }
    if (WF) *(float4*)(Y + (size_t)r * EMB + c4) = make_float4(y[0], y[1], y[2], y[3]);
    __nv_bfloat16 h[4], l[4];
#pragma unroll
    for (int j = 0; j < 4; j++) split1(y[j], h[j], l[j]);
    size_t b = (size_t)r * KS2 + c4;
    *(uint2*)(out + b) = pack4(h[0], h[1], h[2], h[3]);
    *(uint2*)(out + b + 256) = pack4(l[0], l[1], l[2], l[3]);
}

// ====== bf16 HMMA GEMM: C[M,N] (op)= A*B^T, bf16x3 via chunk tables =================
// CTA tile 128x256, 8 warps (2x4), warp tile 64x64. 3-stage cp.async pipeline.
enum { EPI_STORE = 0, EPI_ACC = 1, EPI_SIG = 2 };

#define BM 128
#define BN 256
#define NKC 12
#define STAGE_SZ 49152            // A 16KB + B 32KB
#define SM_GEMM (3 * STAGE_SZ)    // 147456

static __device__ __forceinline__ uint32_t cvtas(const void* p) {
    uint32_t a;
    asm("{ .reg .u64 t; cvta.to.shared.u64 t, %1; cvt.u32.u64 %0, t; }" : "=r"(a) : "l"(p));
    return a;
}
static __device__ __forceinline__ uint32_t swz(uint32_t o) { return o ^ ((o >> 3) & 0x70); }
static __device__ __forceinline__ void cp16(uint32_t d, const void* g, int sz) {
    asm volatile("cp.async.cg.shared.global [%0], [%1], 16, %2;" :: "r"(d), "l"(g), "r"(sz));
}
static __device__ __forceinline__ void ldsm4(uint32_t& d0, uint32_t& d1, uint32_t& d2,
                                             uint32_t& d3, uint32_t a) {
    asm volatile("ldmatrix.sync.aligned.m8n8.x4.shared.b16 {%0,%1,%2,%3}, [%4];"
                 : "=r"(d0), "=r"(d1), "=r"(d2), "=r"(d3) : "r"(a));
}
static __device__ __forceinline__ void mma16816(float* c, uint32_t a0, uint32_t a1,
                                                uint32_t a2, uint32_t a3,
                                                uint32_t b0, uint32_t b1) {
    asm volatile("mma.sync.aligned.m16n8k16.row.col.f32.bf16.bf16.f32 "
                 "{%0,%1,%2,%3}, {%4,%5,%6,%7}, {%8,%9}, {%0,%1,%2,%3};"
                 : "+f"(c[0]), "+f"(c[1]), "+f"(c[2]), "+f"(c[3])
                 : "r"(a0), "r"(a1), "r"(a2), "r"(a3), "r"(b0), "r"(b1));
}

template <int EPI>
__global__ void __launch_bounds__(256, 1)
gemm_bf16(const __nv_bfloat16* __restrict__ A, const __nv_bfloat16* __restrict__ B,
          float* __restrict__ C, int M, int N) {
    extern __shared__ char smem[];
    const uint32_t sb = cvtas(smem);
    const uint32_t stB[3] = { sb, sb + STAGE_SZ, sb + 2 * STAGE_SZ };

    const int tid = threadIdx.x;
    const int lane = tid & 31, wid = tid >> 5;
    const int wm = wid >> 2, wn = wid & 3;
    const int m0 = blockIdx.y * BM, n0 = blockIdx.x * BN;

    // ---- loader: A rows {r0, r0+64} x chunks {c2,c2+1}; B rows {r0+64r} r=0..3 ----
    const int r0 = tid >> 2;
    const int c2 = (tid & 3) * 2;
    uint32_t soA[2][2], soB[4][2];
#pragma unroll
    for (int q = 0; q < 2; q++) {
#pragma unroll
        for (int r = 0; r < 2; r++)
            soA[r][q] = swz((uint32_t)(r0 + r * 64) * 128 + (uint32_t)(c2 + q) * 16);
#pragma unroll
        for (int r = 0; r < 4; r++)
            soB[r][q] = swz((uint32_t)(r0 + r * 64) * 128 + (uint32_t)(c2 + q) * 16);
    }
    int szA[2], szB[4];
    const __nv_bfloat16 *Ag[2], *Bg[4];
#pragma unroll
    for (int r = 0; r < 2; r++) {
        long mr = m0 + r0 + r * 64;
        szA[r] = mr < M ? 16 : 0;
        Ag[r] = A + (size_t)(mr < M ? mr : M - 1) * KS2 + c2 * 8;
    }
#pragma unroll
    for (int r = 0; r < 4; r++) {
        long nr = n0 + r0 + r * 64;
        szB[r] = nr < N ? 16 : 0;
        Bg[r] = B + (size_t)(nr < N ? nr : N - 1) * KS2 + c2 * 8;
    }

    float acc[4][8][4];
#pragma unroll
    for (int i = 0; i < 4; i++)
#pragma unroll
        for (int j = 0; j < 8; j++)
#pragma unroll
            for (int q = 0; q < 4; q++) acc[i][j][q] = 0.f;

    auto issue = [&](uint32_t stBase, int kc) {
        const int ka = c_ka[kc], kb = c_kb[kc];
        const uint32_t aB = stBase, bB_ = stBase + 16384;
#pragma unroll
        for (int q = 0; q < 2; q++) {
#pragma unroll
            for (int r = 0; r < 2; r++)
                cp16(aB + soA[r][q], Ag[r] + ka + q * 8, szA[r]);
#pragma unroll
            for (int r = 0; r < 4; r++)
                cp16(bB_ + soB[r][q], Bg[r] + kb + q * 8, szB[r]);
        }
        asm volatile("cp.async.commit_group;");
    };

    const uint32_t aRow = (uint32_t)(wm * 64 + (lane & 15));
    const uint32_t aChk = (uint32_t)(lane >> 4);
    const uint32_t bRow0 = (uint32_t)(wn * 64 + (lane & 7) + ((lane >> 4) & 1) * 8);
    const uint32_t bChk = (uint32_t)((lane >> 3) & 1);

    auto compute = [&](uint32_t stBase) {
        const uint32_t aB = stBase, bB_ = stBase + 16384;
#pragma unroll
        for (int ks = 0; ks < 4; ks++) {
            uint32_t a[4][4];
#pragma unroll
            for (int mi = 0; mi < 4; mi++) {
                uint32_t o = (aRow + mi * 16) * 128 + (2 * ks + aChk) * 16;
                ldsm4(a[mi][0], a[mi][1], a[mi][2], a[mi][3], aB + swz(o));
            }
            uint32_t bf[8][2];
#pragma unroll
            for (int j = 0; j < 4; j++) {
                uint32_t t0, t1, t2, t3;
                uint32_t o = (bRow0 + j * 16) * 128 + (2 * ks + bChk) * 16;
                ldsm4(t0, t1, t2, t3, bB_ + swz(o));
                bf[2 * j][0] = t0;     bf[2 * j][1] = t1;
                bf[2 * j + 1][0] = t2; bf[2 * j + 1][1] = t3;
            }
#pragma unroll
            for (int mi = 0; mi < 4; mi++)
#pragma unroll
                for (int nj = 0; nj < 8; nj++)
                    mma16816(acc[mi][nj], a[mi][0], a[mi][1], a[mi][2], a[mi][3],
                             bf[nj][0], bf[nj][1]);
        }
    };

    issue(stB[0], 0);
    issue(stB[1], 1);
    auto step = [&](int kc, int st) {
        asm volatile("cp.async.wait_group 1;");
        __syncthreads();
        compute(stB[st]);
        if (kc + 2 < NKC) issue(stB[(st + 2) % 3], kc + 2);
        else asm volatile("cp.async.commit_group;");
    };
#pragma unroll 1
    for (int kc = 0; kc < NKC; kc += 3) {
        step(kc, 0); step(kc + 1, 1); step(kc + 2, 2);
    }

    // epilogue
#pragma unroll
    for (int mi = 0; mi < 4; mi++) {
        int row = m0 + wm * 64 + mi * 16 + (lane >> 2);
#pragma unroll
        for (int nj = 0; nj < 8; nj++) {
            int col = n0 + wn * 64 + nj * 8 + (lane & 3) * 2;
            float* cf = acc[mi][nj];
#pragma unroll
            for (int h = 0; h < 2; h++) {
                int r = row + h * 8;
                if (r >= M) continue;
                float* p = C + (size_t)r * N + col;
#pragma unroll
                for (int q = 0; q < 2; q++) {
                    if (col + q >= N) continue;
                    float v = cf[h * 2 + q];
                    if (EPI == EPI_ACC) v += p[q];
                    if (EPI == EPI_SIG) v = 1.f / (1.f + __expf(-v));
                    p[q] = v;
                }
            }
        }
    }
}

// ---------------- SpMM: agg[row] += val * sup[col] ----------------
__global__ void spmm(const int* __restrict__ rows, const int* __restrict__ cols,
                     const float* __restrict__ vals, const float* __restrict__ sup,
                     float* __restrict__ agg, int ne) {
    int e = blockIdx.x * 4 + (threadIdx.x >> 6);
    if (e >= ne) return;
    int t = threadIdx.x & 63;
    int r = rows[e], c = cols[e];
    float v = vals[e];
    float4 s = *(const float4*)(sup + (size_t)c * EMB + t * 4);
    float4 a = make_float4(v * s.x, v * s.y, v * s.z, v * s.w);
    atomicAdd((float4*)(agg + (size_t)r * EMB + t * 4), a);
}

// ---------------- node batchnorm stats ----------------
__global__ void colstats(const float* __restrict__ X, int n) {
    int c = threadIdx.x;
    int r0 = blockIdx.x * 256;
    int r1 = min(r0 + 256, n);
    float s = 0.f, s2 = 0.f;
    for (int r = r0; r < r1; r++) {
        float v = X[(size_t)r * EMB + c];
        s += v; s2 += v * v;
    }
    atomicAdd(&g_csum[c], s);
    atomicAdd(&g_csq[c], s2);
}

__global__ void bn_final(const float* __restrict__ gamma, const float* __restrict__ beta,
                         float inv_n) {
    int c = threadIdx.x;
    float m = g_csum[c] * inv_n;
    float var = g_csq[c] * inv_n - m * m;
    float sc = rsqrtf(var + BN_EPS) * gamma[c];
    g_scale[c] = sc;
    g_shift[c] = beta[c] - m * sc;
}

// ---------------- score head ----------------
__global__ void vecvec(const float* __restrict__ X, const float* __restrict__ R,
                       const int* __restrict__ e1, const int* __restrict__ ri,
                       float* __restrict__ hr) {
    int b = blockIdx.x;
    int s = threadIdx.x;
    const float* h = X + (size_t)e1[b] * EMB;
    const float* p = R + (size_t)ri[b] * EMB;
    float pr = p[s], pi = p[64 + s], pj = p[128 + s], pk = p[192 + s];
    float inv = rsqrtf(pr * pr + pi * pi + pj * pj + pk * pk);
    pr *= inv; pi *= inv; pj *= inv; pk *= inv;
    float qr = h[s], qi = h[64 + s], qj = h[128 + s], qk = h[192 + s];
    float* o = hr + (size_t)b * EMB;
    o[s]       = qr * pr - qi * pi - qj * pj - qk * pk;
    o[64 + s]  = qi * pr + qr * pi - qk * pj + qj * pk;
    o[128 + s] = qj * pr + qk * pi + qr * pj - qi * pk;
    o[192 + s] = qk * pr - qj * pi + qi * pj + qr * pk;
}

__global__ void __launch_bounds__(1024)
bn_batch(float* __restrict__ hr, const float* __restrict__ gamma,
         const float* __restrict__ beta) {
    __shared__ float ss[4][EMB], sq[4][EMB], sc[EMB], sh[EMB];
    int c = threadIdx.x & 255, g = threadIdx.x >> 8;
    float s = 0.f, s2 = 0.f;
    for (int b = g * 128; b < g * 128 + 128; b++) {
        float v = hr[(size_t)b * EMB + c];
        s += v; s2 += v * v;
    }
    ss[g][c] = s; sq[g][c] = s2;
    __syncthreads();
    if (g == 0) {
        float S = ss[0][c] + ss[1][c] + ss[2][c] + ss[3][c];
        float Q = sq[0][c] + sq[1][c] + sq[2][c] + sq[3][c];
        float m = S * (1.f / BATCH);
        float var = Q * (1.f / BATCH) - m * m;
        float scale = rsqrtf(var + BN_EPS) * gamma[c];
        sc[c] = scale; sh[c] = beta[c] - m * scale;
    }
    __syncthreads();
    float scale = sc[c], shift = sh[c];
    for (int b = g * 128; b < g * 128 + 128; b++)
        hr[(size_t)b * EMB + c] = hr[(size_t)b * EMB + c] * scale + shift;
}

// ---------------- host orchestration ----------------
static void run_score(int s, const int* e1, const int* ri,
                      const float* bsg, const float* bsb,
                      float* XR, float* hr, float* out,
                      __nv_bfloat16* SA1, __nv_bfloat16* hrA) {
    vecvec<<<BATCH, 64>>>(XR, XR + (size_t)N_ENTS * EMB, e1, ri, hr);
    bn_batch<<<1, 1024>>>(hr, bsg + s * EMB, bsb + s * EMB);
    split_hl<<<(BATCH * 64 + 255) / 256, 256>>>(hr, hrA, BATCH * 64);
    dim3 g((N_ENTS + BN - 1) / BN, (BATCH + BM - 1) / BM);   // (196, 4)
    gemm_bf16<EPI_SIG><<<g, 256, SM_GEMM>>>(hrA, SA1,
                                            out + (size_t)s * BATCH * N_ENTS,
                                            BATCH, N_ENTS);
}

extern "C" void kernel_launch(void* const* d_in, const int* in_sizes, int n_in,
                              void* d_out, int out_size) {
    const int*   e1      = (const int*)d_in[0];
    const int*   ri      = (const int*)d_in[1];
    const float* emb     = (const float*)d_in[2];
    const float* gcn1_w  = (const float*)d_in[3];
    const float* gcn2_w  = (const float*)d_in[4];
    const float* g1_gam  = (const float*)d_in[5];
    const float* g1_bet  = (const float*)d_in[6];
    const float* g2_gam  = (const float*)d_in[7];
    const float* g2_bet  = (const float*)d_in[8];
    const float* lin     = (const float*)d_in[9];
    const float* bsg     = (const float*)d_in[10];
    const float* bsb     = (const float*)d_in[11];
    const int*   a_rows  = (const int*)d_in[12];
    const int*   a_cols  = (const int*)d_in[13];
    const float* a_vals  = (const float*)d_in[14];
    const int*   ar_rows = (const int*)d_in[15];
    const int*   ar_cols = (const int*)d_in[16];
    const float* ar_vals = (const float*)d_in[17];
    float* out = (float*)d_out;

    cudaFuncSetAttribute(gemm_bf16<EPI_STORE>, cudaFuncAttributeMaxDynamicSharedMemorySize, SM_GEMM);
    cudaFuncSetAttribute(gemm_bf16<EPI_ACC>,   cudaFuncAttributeMaxDynamicSharedMemorySize, SM_GEMM);
    cudaFuncSetAttribute(gemm_bf16<EPI_SIG>,   cudaFuncAttributeMaxDynamicSharedMemorySize, SM_GEMM);

    float *XR, *sup, *agg, *XRrf, *hr, *HamT, *H1T, *H2T, *csum, *csq;
    __nv_bfloat16 *SA1, *SA2, *SA3, *Wb, *hrA;
    cudaGetSymbolAddress((void**)&XR,   g_XR);
    cudaGetSymbolAddress((void**)&sup,  g_sup);
    cudaGetSymbolAddress((void**)&agg,  g_agg);
    cudaGetSymbolAddress((void**)&XRrf, g_XRrf);
    cudaGetSymbolAddress((void**)&hr,   g_hr);
    cudaGetSymbolAddress((void**)&HamT, g_HamT);
    cudaGetSymbolAddress((void**)&H1T,  g_H1T);
    cudaGetSymbolAddress((void**)&H2T,  g_H2T);
    cudaGetSymbolAddress((void**)&csum, g_csum);
    cudaGetSymbolAddress((void**)&csq,  g_csq);
    cudaGetSymbolAddress((void**)&SA1,  g_SA1);
    cudaGetSymbolAddress((void**)&SA2,  g_SA2);
    cudaGetSymbolAddress((void**)&SA3,  g_SA3);
    cudaGetSymbolAddress((void**)&Wb,   g_Wb);
    cudaGetSymbolAddress((void**)&hrA,  g_hrA);

    cudaMemcpyAsync(XR, emb, (size_t)N_TOT * EMB * sizeof(float),
                    cudaMemcpyDeviceToDevice);

    const dim3 gW(1, (N_TOT + BM - 1) / BM);     // (1, 395)  N=256
    const dim3 gWe(1, (N_ENTS + BM - 1) / BM);   // (1, 391)
    const int BLK_TOT = (N_TOT * 64 + 255) / 256;
    const int BLK_ENT = (N_ENTS * 64 + 255) / 256;
    const int BLK_EMB = (EMB * 64 + 255) / 256;

    // ---- launch order keeps a real GEMM at position #4 for ncu ----
    build_hamT<<<(EMB * EMB + 255) / 256, 256>>>(gcn2_w, HamT);                // #1
    split_hl<<<BLK_EMB, 256>>>(HamT, Wb, EMB * 64);                            // #2
    split_hl<<<BLK_TOT, 256>>>(XR, SA1, N_TOT * 64);                           // #3
    gemm_bf16<EPI_STORE><<<gW, 256, SM_GEMM>>>(SA1, Wb, sup, N_TOT, EMB);      // #4

    run_score(0, e1, ri, bsg, bsb, XR, hr, out, SA1, hrA);

    for (int l = 0; l < 2; l++) {
        // ---- XR branch: XRrf = tanh(bn(segsum(adjr, XR @ Ham(gcn2)))) ----
        if (l > 0) {
            build_hamT<<<(EMB * EMB + 255) / 256, 256>>>(gcn2_w + (size_t)l * 64 * EMB, HamT);
            split_hl<<<BLK_EMB, 256>>>(HamT, Wb, EMB * 64);
            gemm_bf16<EPI_STORE><<<gW, 256, SM_GEMM>>>(SA1, Wb, sup, N_TOT, EMB);
        }
        cudaMemsetAsync(agg, 0, (size_t)N_TOT * EMB * sizeof(float));
        spmm<<<(N_EDGES + 3) / 4, 256>>>(ar_rows, ar_cols, ar_vals, sup, agg, N_EDGES);
        cudaMemsetAsync(csum, 0, EMB * sizeof(float));
        cudaMemsetAsync(csq,  0, EMB * sizeof(float));
        colstats<<<(N_TOT + 255) / 256, EMB>>>(agg, N_TOT);
        bn_final<<<1, EMB>>>(g2_gam + l * EMB, g2_bet + l * EMB, 1.f / N_TOT);
        bn_tanh_split<true><<<BLK_TOT, 256>>>(agg, XRrf, SA2, N_TOT * 64);

        // ---- X branch (SA1 rows [0,N_ENTS) still valid) ----
        build_hamT<<<(EMB * EMB + 255) / 256, 256>>>(gcn1_w + (size_t)l * 64 * EMB, HamT);
        split_hl<<<BLK_EMB, 256>>>(HamT, Wb, EMB * 64);
        gemm_bf16<EPI_STORE><<<gWe, 256, SM_GEMM>>>(SA1, Wb, sup, N_ENTS, EMB);
        cudaMemsetAsync(agg, 0, (size_t)N_ENTS * EMB * sizeof(float));
        spmm<<<(N_EDGES + 3) / 4, 256>>>(a_rows, a_cols, a_vals, sup, agg, N_EDGES);
        cudaMemsetAsync(csum, 0, EMB * sizeof(float));
        cudaMemsetAsync(csq,  0, EMB * sizeof(float));
        colstats<<<(N_ENTS + 255) / 256, EMB>>>(agg, N_ENTS);
        bn_final<<<1, EMB>>>(g1_gam + l * EMB, g1_bet + l * EMB, 1.f / N_ENTS);
        bn_tanh_split<false><<<BLK_ENT, 256>>>(agg, nullptr, SA3, N_ENTS * 64);

        // ---- lin: X_new = Xef @ H1^T + Xrf @ H2^T ----
        build_hamLPT<<<EMB, EMB>>>(lin + (size_t)l * 128 * EMB, H1T, H2T);
        split_hl<<<BLK_EMB, 256>>>(H1T, Wb, EMB * 64);
        gemm_bf16<EPI_STORE><<<gWe, 256, SM_GEMM>>>(SA3, Wb, XR, N_ENTS, EMB);
        split_hl<<<BLK_EMB, 256>>>(H2T, Wb, EMB * 64);
        gemm_bf16<EPI_ACC><<<gWe, 256, SM_GEMM>>>(SA2, Wb, XR, N_ENTS, EMB);
        cudaMemcpyAsync(XR + (size_t)N_ENTS * EMB, XRrf + (size_t)N_ENTS * EMB,
                        (size_t)N_RELS * EMB * sizeof(float),
                        cudaMemcpyDeviceToDevice);

        // refresh SA1 = split(XR): feeds next layer's sup gemms AND the score B-side
        split_hl<<<BLK_TOT, 256>>>(XR, SA1, N_TOT * 64);
        run_score(l + 1, e1, ri, bsg, bsb, XR, hr, out, SA1, hrA);
    }
}

// round 8
// speedup vs baseline: 1.1505x; 1.1505x over previous
#include <cuda_runtime.h>
#include <cuda_bf16.h>
#include <stdint.h>

#define N_ENTS 50000
#define N_RELS 500
#define N_TOT  50500
#define EMB    256
#define N_EDGES 400000
#define BATCH  512
#define BN_EPS 1e-5f
#define KS2    512   // h|l storage width (bf16x3 streams 768 via chunk tables)

// ---------------- scratch (__device__ globals, no allocations) ----------------
__device__ float g_XR[(size_t)N_TOT * EMB];
__device__ float g_sup[(size_t)N_TOT * EMB];    // XR-branch support
__device__ float g_supX[(size_t)N_ENTS * EMB];  // X-branch support
__device__ float g_agg[(size_t)N_TOT * EMB];    // XR-branch segment sum
__device__ float g_aggX[(size_t)N_ENTS * EMB];  // X-branch segment sum
__device__ float g_hr[(size_t)BATCH * EMB];
__device__ float g_HamT[EMB * EMB];
__device__ float g_H1T[EMB * EMB];
__device__ float g_H2T[EMB * EMB];
__device__ float g_csum[2 * EMB];
__device__ float g_csq[2 * EMB];
__device__ float g_scale[2 * EMB];
__device__ float g_shift[2 * EMB];

// h|l split buffers: [n, 512] bf16, cols 0-255 = hi, 256-511 = lo
__device__ __nv_bfloat16 g_SA1[(size_t)N_TOT * KS2];     // split of XR
__device__ __nv_bfloat16 g_SA2[(size_t)N_TOT * KS2];     // split of XRrf
__device__ __nv_bfloat16 g_SA3[(size_t)N_ENTS * KS2];    // split of Xef
__device__ __nv_bfloat16 g_Wb[EMB * KS2];                // split weights (XR/lin1)
__device__ __nv_bfloat16 g_Wb2[EMB * KS2];               // split weights (X/lin2)
__device__ __nv_bfloat16 g_hrA[(size_t)BATCH * KS2];     // split hr

// quaternion block tables
__constant__ int   c_comp[4][4] = {{0,1,2,3},{1,0,3,2},{2,3,0,1},{3,2,1,0}};
__constant__ float c_sign[4][4] = {{ 1.f, 1.f, 1.f, 1.f},
                                   {-1.f, 1.f, 1.f,-1.f},
                                   {-1.f,-1.f, 1.f, 1.f},
                                   {-1.f, 1.f,-1.f, 1.f}};

// bf16x3 chunk schedule (64-half chunks): AhBh x4, AlBh x4, AhBl x4
__constant__ int c_ka[12] = {0,64,128,192, 256,320,384,448, 0,64,128,192};
__constant__ int c_kb[12] = {0,64,128,192, 0,64,128,192, 256,320,384,448};

// ---------------- helpers ----------------
static __device__ __forceinline__ void split1(float x, __nv_bfloat16& h, __nv_bfloat16& l) {
    h = __float2bfloat16(x);
    l = __float2bfloat16(x - __bfloat162float(h));
}
static __device__ __forceinline__ uint2 pack4(__nv_bfloat16 a, __nv_bfloat16 b,
                                              __nv_bfloat16 c, __nv_bfloat16 d) {
    uint2 u;
    u.x = ((uint32_t)__bfloat16_as_ushort(b) << 16) | __bfloat16_as_ushort(a);
    u.y = ((uint32_t)__bfloat16_as_ushort(d) << 16) | __bfloat16_as_ushort(c);
    return u;
}

// ---------------- hamilton builders (store TRANSPOSED: HT[c*K + k]) ----------------
__global__ void build_hamT(const float* __restrict__ W, float* __restrict__ HT) {
    int idx = blockIdx.x * blockDim.x + threadIdx.x;
    if (idx >= EMB * EMB) return;
    int c = idx >> 8, k = idx & 255;
    int a = k >> 6, u = k & 63, b = c >> 6, v = c & 63;
    HT[idx] = c_sign[a][b] * W[u * EMB + c_comp[a][b] * 64 + v];
}

__global__ void build_hamLPT(const float* __restrict__ W, float* __restrict__ H1,
                             float* __restrict__ H2) {
    int c = blockIdx.x, j = threadIdx.x;
    int q = j >> 6, s = j & 63;
    int b = c >> 6, v = c & 63;
    int pe = 128 * q + s;
    int pr = pe + 64;
    int a1 = pe >> 7, u1 = pe & 127;
    int a2 = pr >> 7, u2 = pr & 127;
    H1[c * EMB + j] = c_sign[a1][b] * W[u1 * EMB + c_comp[a1][b] * 64 + v];
    H2[c * EMB + j] = c_sign[a2][b] * W[u2 * EMB + c_comp[a2][b] * 64 + v];
}

// ---------------- h|l split conversion ----------------
__global__ void split_hl(const float* __restrict__ in, __nv_bfloat16* __restrict__ out,
                         int n64) {
    int i = blockIdx.x * blockDim.x + threadIdx.x;
    if (i >= n64) return;
    int r = i >> 6, c4 = (i & 63) << 2;
    float4 x = *(const float4*)(in + (size_t)r * EMB + c4);
    __nv_bfloat16 h[4], l[4];
    split1(x.x, h[0], l[0]); split1(x.y, h[1], l[1]);
    split1(x.z, h[2], l[2]); split1(x.w, h[3], l[3]);
    size_t b = (size_t)r * KS2 + c4;
    *(uint2*)(out + b) = pack4(h[0], h[1], h[2], h[3]);
    *(uint2*)(out + b + 256) = pack4(l[0], l[1], l[2], l[3]);
}

// bn+tanh fused with h|l split output.
// WRR: write float rows >= N_ENTS into XRout (the R-row update, in place of XRrf+memcpy)
template <bool WRR>
__global__ void bn_tanh_split(const float* __restrict__ X, float* __restrict__ XRout,
                              __nv_bfloat16* __restrict__ out, int so, int n64) {
    int i = blockIdx.x * blockDim.x + threadIdx.x;
    if (i >= n64) return;
    int r = i >> 6, c4 = (i & 63) << 2;
    float4 x = *(const float4*)(X + (size_t)r * EMB + c4);
    float y[4];
    float* xs = &x.x;
#pragma unroll
    for (int j = 0; j < 4; j++) {
        float z = xs[j] * g_scale[so + c4 + j] + g_shift[so + c4 + j];
        float e = __expf(-2.f * fabsf(z));
        float t = (1.f - e) / (1.f + e);
        y[j] = copysignf(t, z);
    }
    if (WRR && r >= N_ENTS)
        *(float4*)(XRout + (size_t)r * EMB + c4) = make_float4(y[0], y[1], y[2], y[3]);
    __nv_bfloat16 h[4], l[4];
#pragma unroll
    for (int j = 0; j < 4; j++) split1(y[j], h[j], l[j]);
    size_t b = (size_t)r * KS2 + c4;
    *(uint2*)(out + b) = pack4(h[0], h[1], h[2], h[3]);
    *(uint2*)(out + b + 256) = pack4(l[0], l[1], l[2], l[3]);
}

// ====== bf16 HMMA GEMM (R6 config): 128x128 tile, 64x32 warps, 3-stage, 2 CTA/SM ======
enum { EPI_STORE = 0, EPI_ACC = 1, EPI_SIG = 2 };

#define BM 128
#define BN 128
#define NKC 12
#define STAGE_SZ 32768            // A 16KB + B 16KB
#define SM_GEMM (3 * STAGE_SZ)    // 98304

static __device__ __forceinline__ uint32_t cvtas(const void* p) {
    uint32_t a;
    asm("{ .reg .u64 t; cvta.to.shared.u64 t, %1; cvt.u32.u64 %0, t; }" : "=r"(a) : "l"(p));
    return a;
}
static __device__ __forceinline__ uint32_t swz(uint32_t o) { return o ^ ((o >> 3) & 0x70); }
static __device__ __forceinline__ void cp16(uint32_t d, const void* g, int sz) {
    asm volatile("cp.async.cg.shared.global [%0], [%1], 16, %2;" :: "r"(d), "l"(g), "r"(sz));
}
static __device__ __forceinline__ void ldsm4(uint32_t& d0, uint32_t& d1, uint32_t& d2,
                                             uint32_t& d3, uint32_t a) {
    asm volatile("ldmatrix.sync.aligned.m8n8.x4.shared.b16 {%0,%1,%2,%3}, [%4];"
                 : "=r"(d0), "=r"(d1), "=r"(d2), "=r"(d3) : "r"(a));
}
static __device__ __forceinline__ void mma16816(float* c, uint32_t a0, uint32_t a1,
                                                uint32_t a2, uint32_t a3,
                                                uint32_t b0, uint32_t b1) {
    asm volatile("mma.sync.aligned.m16n8k16.row.col.f32.bf16.bf16.f32 "
                 "{%0,%1,%2,%3}, {%4,%5,%6,%7}, {%8,%9}, {%0,%1,%2,%3};"
                 : "+f"(c[0]), "+f"(c[1]), "+f"(c[2]), "+f"(c[3])
                 : "r"(a0), "r"(a1), "r"(a2), "r"(a3), "r"(b0), "r"(b1));
}

template <int EPI>
__global__ void __launch_bounds__(256, 2)
gemm_bf16(const __nv_bfloat16* __restrict__ A, const __nv_bfloat16* __restrict__ B,
          float* __restrict__ C, int M, int N) {
    extern __shared__ char smem[];
    const uint32_t sb = cvtas(smem);
    const uint32_t stB[3] = { sb, sb + STAGE_SZ, sb + 2 * STAGE_SZ };

    const int tid = threadIdx.x;
    const int lane = tid & 31, wid = tid >> 5;
    const int wm = wid >> 2, wn = wid & 3;
    const int m0 = blockIdx.y * BM, n0 = blockIdx.x * BN;

    // loader: rows {r0, r0+64}, 16B chunks {c2, c2+1}
    const int r0 = tid >> 2;
    const int c2 = (tid & 3) * 2;
    uint32_t soff[2][2];
#pragma unroll
    for (int r = 0; r < 2; r++)
#pragma unroll
        for (int q = 0; q < 2; q++)
            soff[r][q] = swz((uint32_t)(r0 + r * 64) * 128 + (uint32_t)(c2 + q) * 16);

    int szA[2], szB[2];
    const __nv_bfloat16 *Ag[2], *Bg[2];
#pragma unroll
    for (int r = 0; r < 2; r++) {
        long mr = m0 + r0 + r * 64, nr = n0 + r0 + r * 64;
        szA[r] = mr < M ? 16 : 0;
        szB[r] = nr < N ? 16 : 0;
        Ag[r] = A + (size_t)(mr < M ? mr : M - 1) * KS2 + c2 * 8;
        Bg[r] = B + (size_t)(nr < N ? nr : N - 1) * KS2 + c2 * 8;
    }

    float acc[4][4][4];
#pragma unroll
    for (int i = 0; i < 4; i++)
#pragma unroll
        for (int j = 0; j < 4; j++)
#pragma unroll
            for (int q = 0; q < 4; q++) acc[i][j][q] = 0.f;

    auto issue = [&](uint32_t stBase, int kc) {
        const int ka = c_ka[kc], kb = c_kb[kc];
        const uint32_t aB = stBase, bB_ = stBase + 16384;
#pragma unroll
        for (int q = 0; q < 2; q++)
#pragma unroll
            for (int r = 0; r < 2; r++) {
                cp16(aB + soff[r][q], Ag[r] + ka + q * 8, szA[r]);
                cp16(bB_ + soff[r][q], Bg[r] + kb + q * 8, szB[r]);
            }
        asm volatile("cp.async.commit_group;");
    };

    const uint32_t aRow = (uint32_t)(wm * 64 + (lane & 15));
    const uint32_t aChk = (uint32_t)(lane >> 4);
    const uint32_t bRow0 = (uint32_t)(wn * 32 + (lane & 7) + ((lane >> 4) & 1) * 8);
    const uint32_t bChk = (uint32_t)((lane >> 3) & 1);

    auto compute = [&](uint32_t stBase) {
        const uint32_t aB = stBase, bB_ = stBase + 16384;
#pragma unroll
        for (int ks = 0; ks < 4; ks++) {
            uint32_t a[4][4];
#pragma unroll
            for (int mi = 0; mi < 4; mi++) {
                uint32_t o = (aRow + mi * 16) * 128 + (2 * ks + aChk) * 16;
                ldsm4(a[mi][0], a[mi][1], a[mi][2], a[mi][3], aB + swz(o));
            }
            uint32_t bf[4][2];
#pragma unroll
            for (int j = 0; j < 2; j++) {
                uint32_t t0, t1, t2, t3;
                uint32_t o = (bRow0 + j * 16) * 128 + (2 * ks + bChk) * 16;
                ldsm4(t0, t1, t2, t3, bB_ + swz(o));
                bf[2 * j][0] = t0;     bf[2 * j][1] = t1;
                bf[2 * j + 1][0] = t2; bf[2 * j + 1][1] = t3;
            }
#pragma unroll
            for (int mi = 0; mi < 4; mi++)
#pragma unroll
                for (int nj = 0; nj < 4; nj++)
                    mma16816(acc[mi][nj], a[mi][0], a[mi][1], a[mi][2], a[mi][3],
                             bf[nj][0], bf[nj][1]);
        }
    };

    issue(stB[0], 0);
    issue(stB[1], 1);
    auto step = [&](int kc, int st) {
        asm volatile("cp.async.wait_group 1;");
        __syncthreads();
        compute(stB[st]);
        if (kc + 2 < NKC) issue(stB[(st + 2) % 3], kc + 2);
        else asm volatile("cp.async.commit_group;");
    };
#pragma unroll 1
    for (int kc = 0; kc < NKC; kc += 3) {
        step(kc, 0); step(kc + 1, 1); step(kc + 2, 2);
    }

    // epilogue
#pragma unroll
    for (int mi = 0; mi < 4; mi++) {
        int row = m0 + wm * 64 + mi * 16 + (lane >> 2);
#pragma unroll
        for (int nj = 0; nj < 4; nj++) {
            int col = n0 + wn * 32 + nj * 8 + (lane & 3) * 2;
            float* cf = acc[mi][nj];
#pragma unroll
            for (int h = 0; h < 2; h++) {
                int r = row + h * 8;
                if (r >= M) continue;
                float* p = C + (size_t)r * N + col;
#pragma unroll
                for (int q = 0; q < 2; q++) {
                    if (col + q >= N) continue;
                    float v = cf[h * 2 + q];
                    if (EPI == EPI_ACC) v += p[q];
                    if (EPI == EPI_SIG) v = 1.f / (1.f + __expf(-v));
                    p[q] = v;
                }
            }
        }
    }
}

// ---------------- merged SpMM over both graphs ----------------
__global__ void spmm2(const int* __restrict__ r1, const int* __restrict__ c1,
                      const float* __restrict__ v1, const float* __restrict__ s1,
                      float* __restrict__ a1,
                      const int* __restrict__ r2, const int* __restrict__ c2,
                      const float* __restrict__ v2, const float* __restrict__ s2,
                      float* __restrict__ a2) {
    int e = blockIdx.x * 4 + (threadIdx.x >> 6);
    int t = threadIdx.x & 63;
    const int *R, *C;
    const float *V, *S;
    float* A;
    if (e < N_EDGES) { R = r1; C = c1; V = v1; S = s1; A = a1; }
    else { e -= N_EDGES; if (e >= N_EDGES) return; R = r2; C = c2; V = v2; S = s2; A = a2; }
    int r = R[e], c = C[e];
    float v = V[e];
    float4 s = *(const float4*)(S + (size_t)c * EMB + t * 4);
    float4 a = make_float4(v * s.x, v * s.y, v * s.z, v * s.w);
    atomicAdd((float4*)(A + (size_t)r * EMB + t * 4), a);
}

// ---------------- merged node batchnorm stats (both branches) ----------------
#define NB_XR 198   // ceil(N_TOT/256)
#define NB_X  196   // ceil(N_ENTS/256)
__global__ void colstats2(const float* __restrict__ aggXR, const float* __restrict__ aggX) {
    int c = threadIdx.x;
    int b = blockIdx.x;
    const float* X;
    int r0, r1, off;
    if (b < NB_XR) { X = aggXR; r0 = b * 256; r1 = min(r0 + 256, N_TOT); off = 0; }
    else { X = aggX; r0 = (b - NB_XR) * 256; r1 = min(r0 + 256, N_ENTS); off = 256; }
    float s = 0.f, s2 = 0.f;
    for (int r = r0; r < r1; r++) {
        float v = X[(size_t)r * EMB + c];
        s += v; s2 += v * v;
    }
    atomicAdd(&g_csum[off + c], s);
    atomicAdd(&g_csq[off + c], s2);
}

__global__ void bn_final2(const float* __restrict__ g2g, const float* __restrict__ g2b,
                          const float* __restrict__ g1g, const float* __restrict__ g1b) {
    int c = threadIdx.x;   // 0..511
    float inv_n = c < 256 ? (1.f / N_TOT) : (1.f / N_ENTS);
    float gam = c < 256 ? g2g[c] : g1g[c - 256];
    float bet = c < 256 ? g2b[c] : g1b[c - 256];
    float m = g_csum[c] * inv_n;
    float var = g_csq[c] * inv_n - m * m;
    float sc = rsqrtf(var + BN_EPS) * gam;
    g_scale[c] = sc;
    g_shift[c] = bet - m * sc;
}

// ---------------- score head ----------------
__global__ void vecvec(const float* __restrict__ X, const float* __restrict__ R,
                       const int* __restrict__ e1, const int* __restrict__ ri,
                       float* __restrict__ hr) {
    int b = blockIdx.x;
    int s = threadIdx.x;
    const float* h = X + (size_t)e1[b] * EMB;
    const float* p = R + (size_t)ri[b] * EMB;
    float pr = p[s], pi = p[64 + s], pj = p[128 + s], pk = p[192 + s];
    float inv = rsqrtf(pr * pr + pi * pi + pj * pj + pk * pk);
    pr *= inv; pi *= inv; pj *= inv; pk *= inv;
    float qr = h[s], qi = h[64 + s], qj = h[128 + s], qk = h[192 + s];
    float* o = hr + (size_t)b * EMB;
    o[s]       = qr * pr - qi * pi - qj * pj - qk * pk;
    o[64 + s]  = qi * pr + qr * pi - qk * pj + qj * pk;
    o[128 + s] = qj * pr + qk * pi + qr * pj - qi * pk;
    o[192 + s] = qk * pr - qj * pi + qi * pj + qr * pk;
}

__global__ void __launch_bounds__(1024)
bn_batch(float* __restrict__ hr, const float* __restrict__ gamma,
         const float* __restrict__ beta) {
    __shared__ float ss[4][EMB], sq[4][EMB], sc[EMB], sh[EMB];
    int c = threadIdx.x & 255, g = threadIdx.x >> 8;
    float s = 0.f, s2 = 0.f;
    for (int b = g * 128; b < g * 128 + 128; b++) {
        float v = hr[(size_t)b * EMB + c];
        s += v; s2 += v * v;
    }
    ss[g][c] = s; sq[g][c] = s2;
    __syncthreads();
    if (g == 0) {
        float S = ss[0][c] + ss[1][c] + ss[2][c] + ss[3][c];
        float Q = sq[0][c] + sq[1][c] + sq[2][c] + sq[3][c];
        float m = S * (1.f / BATCH);
        float var = Q * (1.f / BATCH) - m * m;
        float scale = rsqrtf(var + BN_EPS) * gamma[c];
        sc[c] = scale; sh[c] = beta[c] - m * scale;
    }
    __syncthreads();
    float scale = sc[c], shift = sh[c];
    for (int b = g * 128; b < g * 128 + 128; b++)
        hr[(size_t)b * EMB + c] = hr[(size_t)b * EMB + c] * scale + shift;
}

// ---------------- host orchestration ----------------
static void run_score(int s, const int* e1, const int* ri,
                      const float* bsg, const float* bsb,
                      float* XR, float* hr, float* out,
                      __nv_bfloat16* SA1, __nv_bfloat16* hrA) {
    vecvec<<<BATCH, 64>>>(XR, XR + (size_t)N_ENTS * EMB, e1, ri, hr);
    bn_batch<<<1, 1024>>>(hr, bsg + s * EMB, bsb + s * EMB);
    split_hl<<<(BATCH * 64 + 255) / 256, 256>>>(hr, hrA, BATCH * 64);
    dim3 g((N_ENTS + BN - 1) / BN, (BATCH + BM - 1) / BM);   // (391, 4)
    gemm_bf16<EPI_SIG><<<g, 256, SM_GEMM>>>(hrA, SA1,
                                            out + (size_t)s * BATCH * N_ENTS,
                                            BATCH, N_ENTS);
}

extern "C" void kernel_launch(void* const* d_in, const int* in_sizes, int n_in,
                              void* d_out, int out_size) {
    const int*   e1      = (const int*)d_in[0];
    const int*   ri      = (const int*)d_in[1];
    const float* emb     = (const float*)d_in[2];
    const float* gcn1_w  = (const float*)d_in[3];
    const float* gcn2_w  = (const float*)d_in[4];
    const float* g1_gam  = (const float*)d_in[5];
    const float* g1_bet  = (const float*)d_in[6];
    const float* g2_gam  = (const float*)d_in[7];
    const float* g2_bet  = (const float*)d_in[8];
    const float* lin     = (const float*)d_in[9];
    const float* bsg     = (const float*)d_in[10];
    const float* bsb     = (const float*)d_in[11];
    const int*   a_rows  = (const int*)d_in[12];
    const int*   a_cols  = (const int*)d_in[13];
    const float* a_vals  = (const float*)d_in[14];
    const int*   ar_rows = (const int*)d_in[15];
    const int*   ar_cols = (const int*)d_in[16];
    const float* ar_vals = (const float*)d_in[17];
    float* out = (float*)d_out;

    cudaFuncSetAttribute(gemm_bf16<EPI_STORE>, cudaFuncAttributeMaxDynamicSharedMemorySize, SM_GEMM);
    cudaFuncSetAttribute(gemm_bf16<EPI_ACC>,   cudaFuncAttributeMaxDynamicSharedMemorySize, SM_GEMM);
    cudaFuncSetAttribute(gemm_bf16<EPI_SIG>,   cudaFuncAttributeMaxDynamicSharedMemorySize, SM_GEMM);

    float *XR, *sup, *supX, *agg, *aggX, *hr, *HamT, *H1T, *H2T, *csum, *csq;
    __nv_bfloat16 *SA1, *SA2, *SA3, *Wb, *Wb2, *hrA;
    cudaGetSymbolAddress((void**)&XR,   g_XR);
    cudaGetSymbolAddress((void**)&sup,  g_sup);
    cudaGetSymbolAddress((void**)&supX, g_supX);
    cudaGetSymbolAddress((void**)&agg,  g_agg);
    cudaGetSymbolAddress((void**)&aggX, g_aggX);
    cudaGetSymbolAddress((void**)&hr,   g_hr);
    cudaGetSymbolAddress((void**)&HamT, g_HamT);
    cudaGetSymbolAddress((void**)&H1T,  g_H1T);
    cudaGetSymbolAddress((void**)&H2T,  g_H2T);
    cudaGetSymbolAddress((void**)&csum, g_csum);
    cudaGetSymbolAddress((void**)&csq,  g_csq);
    cudaGetSymbolAddress((void**)&SA1,  g_SA1);
    cudaGetSymbolAddress((void**)&SA2,  g_SA2);
    cudaGetSymbolAddress((void**)&SA3,  g_SA3);
    cudaGetSymbolAddress((void**)&Wb,   g_Wb);
    cudaGetSymbolAddress((void**)&Wb2,  g_Wb2);
    cudaGetSymbolAddress((void**)&hrA,  g_hrA);

    cudaMemcpyAsync(XR, emb, (size_t)N_TOT * EMB * sizeof(float),
                    cudaMemcpyDeviceToDevice);

    const dim3 gW(EMB / BN, (N_TOT + BM - 1) / BM);     // (2, 395)
    const dim3 gWe(EMB / BN, (N_ENTS + BM - 1) / BM);   // (2, 391)
    const int BLK_TOT = (N_TOT * 64 + 255) / 256;
    const int BLK_ENT = (N_ENTS * 64 + 255) / 256;
    const int BLK_EMB = (EMB * 64 + 255) / 256;

    // prologue — keeps a real GEMM at launch #4 for ncu
    build_hamT<<<(EMB * EMB + 255) / 256, 256>>>(gcn2_w, HamT);        // #1
    split_hl<<<BLK_EMB, 256>>>(HamT, Wb, EMB * 64);                    // #2
    split_hl<<<BLK_TOT, 256>>>(XR, SA1, N_TOT * 64);                   // #3

    for (int l = 0; l < 2; l++) {
        // ---- both branch sup GEMMs ----
        if (l > 0) {
            build_hamT<<<(EMB * EMB + 255) / 256, 256>>>(gcn2_w + (size_t)l * 64 * EMB, HamT);
            split_hl<<<BLK_EMB, 256>>>(HamT, Wb, EMB * 64);
        }
        gemm_bf16<EPI_STORE><<<gW, 256, SM_GEMM>>>(SA1, Wb, sup, N_TOT, EMB);   // #4 at l=0
        build_hamT<<<(EMB * EMB + 255) / 256, 256>>>(gcn1_w + (size_t)l * 64 * EMB, H1T);
        split_hl<<<BLK_EMB, 256>>>(H1T, Wb2, EMB * 64);
        gemm_bf16<EPI_STORE><<<gWe, 256, SM_GEMM>>>(SA1, Wb2, supX, N_ENTS, EMB);

        if (l == 0) run_score(0, e1, ri, bsg, bsb, XR, hr, out, SA1, hrA);

        // ---- merged segment-sum + stats ----
        cudaMemsetAsync(agg,  0, (size_t)N_TOT * EMB * sizeof(float));
        cudaMemsetAsync(aggX, 0, (size_t)N_ENTS * EMB * sizeof(float));
        spmm2<<<(2 * N_EDGES + 3) / 4, 256>>>(ar_rows, ar_cols, ar_vals, sup, agg,
                                              a_rows, a_cols, a_vals, supX, aggX);
        cudaMemsetAsync(csum, 0, 2 * EMB * sizeof(float));
        cudaMemsetAsync(csq,  0, 2 * EMB * sizeof(float));
        colstats2<<<NB_XR + NB_X, EMB>>>(agg, aggX);
        bn_final2<<<1, 2 * EMB>>>(g2_gam + l * EMB, g2_bet + l * EMB,
                                  g1_gam + l * EMB, g1_bet + l * EMB);
        // XRrf: split into SA2, R-rows float straight into XR
        bn_tanh_split<true><<<BLK_TOT, 256>>>(agg, XR, SA2, 0, N_TOT * 64);
        // Xef: split into SA3
        bn_tanh_split<false><<<BLK_ENT, 256>>>(aggX, nullptr, SA3, 256, N_ENTS * 64);

        // ---- lin: X_new = Xef @ H1^T + Xrf @ H2^T ----
        build_hamLPT<<<EMB, EMB>>>(lin + (size_t)l * 128 * EMB, H1T, H2T);
        split_hl<<<BLK_EMB, 256>>>(H1T, Wb, EMB * 64);
        split_hl<<<BLK_EMB, 256>>>(H2T, Wb2, EMB * 64);
        gemm_bf16<EPI_STORE><<<gWe, 256, SM_GEMM>>>(SA3, Wb, XR, N_ENTS, EMB);
        gemm_bf16<EPI_ACC><<<gWe, 256, SM_GEMM>>>(SA2, Wb2, XR, N_ENTS, EMB);

        // refresh SA1 = split(XR): feeds next layer's sup gemms AND the score B-side
        split_hl<<<BLK_TOT, 256>>>(XR, SA1, N_TOT * 64);
        run_score(l + 1, e1, ri, bsg, bsb, XR, hr, out, SA1, hrA);
    }
}

// round 9
// speedup vs baseline: 1.2057x; 1.0480x over previous
#include <cuda_runtime.h>
#include <cuda_bf16.h>
#include <stdint.h>

#define N_ENTS 50000
#define N_RELS 500
#define N_TOT  50500
#define EMB    256
#define N_EDGES 400000
#define BATCH  512
#define BN_EPS 1e-5f
#define KS2    512   // h|l storage width (bf16x3 streams 768 via chunk tables)

// ---------------- scratch (__device__ globals, no allocations) ----------------
__device__ float g_XR[(size_t)N_TOT * EMB];
__device__ float g_sup[(size_t)N_TOT * EMB];    // XR-branch support
__device__ float g_supX[(size_t)N_ENTS * EMB];  // X-branch support
__device__ float g_agg[(size_t)N_TOT * EMB];    // XR-branch segment sum
__device__ float g_aggX[(size_t)N_ENTS * EMB];  // X-branch segment sum
__device__ float g_hr[(size_t)BATCH * EMB];
__device__ float g_HamT[EMB * EMB];
__device__ float g_H1T[EMB * EMB];
__device__ float g_H2T[EMB * EMB];
__device__ float g_csum[2 * EMB];
__device__ float g_csq[2 * EMB];
__device__ float g_scale[2 * EMB];
__device__ float g_shift[2 * EMB];

// h|l split buffers: [n, 512] bf16, cols 0-255 = hi, 256-511 = lo
__device__ __nv_bfloat16 g_SA1[(size_t)N_TOT * KS2];     // split of XR
__device__ __nv_bfloat16 g_SA2[(size_t)N_TOT * KS2];     // split of XRrf
__device__ __nv_bfloat16 g_SA3[(size_t)N_ENTS * KS2];    // split of Xef
__device__ __nv_bfloat16 g_Wb[EMB * KS2];                // split weights (XR/lin1)
__device__ __nv_bfloat16 g_Wb2[EMB * KS2];               // split weights (X/lin2)
__device__ __nv_bfloat16 g_hrA[(size_t)BATCH * KS2];     // split hr

// quaternion block tables
__constant__ int   c_comp[4][4] = {{0,1,2,3},{1,0,3,2},{2,3,0,1},{3,2,1,0}};
__constant__ float c_sign[4][4] = {{ 1.f, 1.f, 1.f, 1.f},
                                   {-1.f, 1.f, 1.f,-1.f},
                                   {-1.f,-1.f, 1.f, 1.f},
                                   {-1.f, 1.f,-1.f, 1.f}};

// bf16x3 chunk schedule (64-half chunks): AhBh x4, AlBh x4, AhBl x4
__constant__ int c_ka[12] = {0,64,128,192, 256,320,384,448, 0,64,128,192};
__constant__ int c_kb[12] = {0,64,128,192, 0,64,128,192, 256,320,384,448};

// ---------------- helpers ----------------
static __device__ __forceinline__ void split1(float x, __nv_bfloat16& h, __nv_bfloat16& l) {
    h = __float2bfloat16(x);
    l = __float2bfloat16(x - __bfloat162float(h));
}
static __device__ __forceinline__ uint2 pack4(__nv_bfloat16 a, __nv_bfloat16 b,
                                              __nv_bfloat16 c, __nv_bfloat16 d) {
    uint2 u;
    u.x = ((uint32_t)__bfloat16_as_ushort(b) << 16) | __bfloat16_as_ushort(a);
    u.y = ((uint32_t)__bfloat16_as_ushort(d) << 16) | __bfloat16_as_ushort(c);
    return u;
}

// ---------------- hamilton builders (store TRANSPOSED: HT[c*K + k]) ----------------
__global__ void build_hamT(const float* __restrict__ W, float* __restrict__ HT) {
    int idx = blockIdx.x * blockDim.x + threadIdx.x;
    if (idx >= EMB * EMB) return;
    int c = idx >> 8, k = idx & 255;
    int a = k >> 6, u = k & 63, b = c >> 6, v = c & 63;
    HT[idx] = c_sign[a][b] * W[u * EMB + c_comp[a][b] * 64 + v];
}

__global__ void build_hamLPT(const float* __restrict__ W, float* __restrict__ H1,
                             float* __restrict__ H2) {
    int c = blockIdx.x, j = threadIdx.x;
    int q = j >> 6, s = j & 63;
    int b = c >> 6, v = c & 63;
    int pe = 128 * q + s;
    int pr = pe + 64;
    int a1 = pe >> 7, u1 = pe & 127;
    int a2 = pr >> 7, u2 = pr & 127;
    H1[c * EMB + j] = c_sign[a1][b] * W[u1 * EMB + c_comp[a1][b] * 64 + v];
    H2[c * EMB + j] = c_sign[a2][b] * W[u2 * EMB + c_comp[a2][b] * 64 + v];
}

// ---------------- h|l split conversion ----------------
__global__ void split_hl(const float* __restrict__ in, __nv_bfloat16* __restrict__ out,
                         int n64) {
    int i = blockIdx.x * blockDim.x + threadIdx.x;
    if (i >= n64) return;
    int r = i >> 6, c4 = (i & 63) << 2;
    float4 x = *(const float4*)(in + (size_t)r * EMB + c4);
    __nv_bfloat16 h[4], l[4];
    split1(x.x, h[0], l[0]); split1(x.y, h[1], l[1]);
    split1(x.z, h[2], l[2]); split1(x.w, h[3], l[3]);
    size_t b = (size_t)r * KS2 + c4;
    *(uint2*)(out + b) = pack4(h[0], h[1], h[2], h[3]);
    *(uint2*)(out + b + 256) = pack4(l[0], l[1], l[2], l[3]);
}

// bn+tanh fused with h|l split output.
// WRR: write float rows >= N_ENTS into XRout (the R-row update)
template <bool WRR>
__global__ void bn_tanh_split(const float* __restrict__ X, float* __restrict__ XRout,
                              __nv_bfloat16* __restrict__ out, int so, int n64) {
    int i = blockIdx.x * blockDim.x + threadIdx.x;
    if (i >= n64) return;
    int r = i >> 6, c4 = (i & 63) << 2;
    float4 x = *(const float4*)(X + (size_t)r * EMB + c4);
    float y[4];
    float* xs = &x.x;
#pragma unroll
    for (int j = 0; j < 4; j++) {
        float z = xs[j] * g_scale[so + c4 + j] + g_shift[so + c4 + j];
        float e = __expf(-2.f * fabsf(z));
        float t = (1.f - e) / (1.f + e);
        y[j] = copysignf(t, z);
    }
    if (WRR && r >= N_ENTS)
        *(float4*)(XRout + (size_t)r * EMB + c4) = make_float4(y[0], y[1], y[2], y[3]);
    __nv_bfloat16 h[4], l[4];
#pragma unroll
    for (int j = 0; j < 4; j++) split1(y[j], h[j], l[j]);
    size_t b = (size_t)r * KS2 + c4;
    *(uint2*)(out + b) = pack4(h[0], h[1], h[2], h[3]);
    *(uint2*)(out + b + 256) = pack4(l[0], l[1], l[2], l[3]);
}

// ====== bf16 HMMA GEMM: 128x128 tile, 64x32 warps, 3-stage, 2 CTA/SM ======
enum { EPI_STORE = 0, EPI_ACC = 1, EPI_SIG = 2 };

#define BM 128
#define BN 128
#define NKC 12
#define STAGE_SZ 32768            // A 16KB + B 16KB
#define SM_GEMM (3 * STAGE_SZ)    // 98304

static __device__ __forceinline__ uint32_t cvtas(const void* p) {
    uint32_t a;
    asm("{ .reg .u64 t; cvta.to.shared.u64 t, %1; cvt.u32.u64 %0, t; }" : "=r"(a) : "l"(p));
    return a;
}
static __device__ __forceinline__ uint32_t swz(uint32_t o) { return o ^ ((o >> 3) & 0x70); }
static __device__ __forceinline__ void cp16(uint32_t d, const void* g, int sz) {
    asm volatile("cp.async.cg.shared.global [%0], [%1], 16, %2;" :: "r"(d), "l"(g), "r"(sz));
}
static __device__ __forceinline__ void ldsm4(uint32_t& d0, uint32_t& d1, uint32_t& d2,
                                             uint32_t& d3, uint32_t a) {
    asm volatile("ldmatrix.sync.aligned.m8n8.x4.shared.b16 {%0,%1,%2,%3}, [%4];"
                 : "=r"(d0), "=r"(d1), "=r"(d2), "=r"(d3) : "r"(a));
}
static __device__ __forceinline__ void mma16816(float* c, uint32_t a0, uint32_t a1,
                                                uint32_t a2, uint32_t a3,
                                                uint32_t b0, uint32_t b1) {
    asm volatile("mma.sync.aligned.m16n8k16.row.col.f32.bf16.bf16.f32 "
                 "{%0,%1,%2,%3}, {%4,%5,%6,%7}, {%8,%9}, {%0,%1,%2,%3};"
                 : "+f"(c[0]), "+f"(c[1]), "+f"(c[2]), "+f"(c[3])
                 : "r"(a0), "r"(a1), "r"(a2), "r"(a3), "r"(b0), "r"(b1));
}

template <int EPI>
__global__ void __launch_bounds__(256, 2)
gemm_bf16(const __nv_bfloat16* __restrict__ A, const __nv_bfloat16* __restrict__ B,
          float* __restrict__ C, int M, int N) {
    extern __shared__ char smem[];
    const uint32_t sb = cvtas(smem);
    const uint32_t stB[3] = { sb, sb + STAGE_SZ, sb + 2 * STAGE_SZ };

    const int tid = threadIdx.x;
    const int lane = tid & 31, wid = tid >> 5;
    const int wm = wid >> 2, wn = wid & 3;
    const int m0 = blockIdx.y * BM, n0 = blockIdx.x * BN;

    const int r0 = tid >> 2;
    const int c2 = (tid & 3) * 2;
    uint32_t soff[2][2];
#pragma unroll
    for (int r = 0; r < 2; r++)
#pragma unroll
        for (int q = 0; q < 2; q++)
            soff[r][q] = swz((uint32_t)(r0 + r * 64) * 128 + (uint32_t)(c2 + q) * 16);

    int szA[2], szB[2];
    const __nv_bfloat16 *Ag[2], *Bg[2];
#pragma unroll
    for (int r = 0; r < 2; r++) {
        long mr = m0 + r0 + r * 64, nr = n0 + r0 + r * 64;
        szA[r] = mr < M ? 16 : 0;
        szB[r] = nr < N ? 16 : 0;
        Ag[r] = A + (size_t)(mr < M ? mr : M - 1) * KS2 + c2 * 8;
        Bg[r] = B + (size_t)(nr < N ? nr : N - 1) * KS2 + c2 * 8;
    }

    float acc[4][4][4];
#pragma unroll
    for (int i = 0; i < 4; i++)
#pragma unroll
        for (int j = 0; j < 4; j++)
#pragma unroll
            for (int q = 0; q < 4; q++) acc[i][j][q] = 0.f;

    auto issue = [&](uint32_t stBase, int kc) {
        const int ka = c_ka[kc], kb = c_kb[kc];
        const uint32_t aB = stBase, bB_ = stBase + 16384;
#pragma unroll
        for (int q = 0; q < 2; q++)
#pragma unroll
            for (int r = 0; r < 2; r++) {
                cp16(aB + soff[r][q], Ag[r] + ka + q * 8, szA[r]);
                cp16(bB_ + soff[r][q], Bg[r] + kb + q * 8, szB[r]);
            }
        asm volatile("cp.async.commit_group;");
    };

    const uint32_t aRow = (uint32_t)(wm * 64 + (lane & 15));
    const uint32_t aChk = (uint32_t)(lane >> 4);
    const uint32_t bRow0 = (uint32_t)(wn * 32 + (lane & 7) + ((lane >> 4) & 1) * 8);
    const uint32_t bChk = (uint32_t)((lane >> 3) & 1);

    auto compute = [&](uint32_t stBase) {
        const uint32_t aB = stBase, bB_ = stBase + 16384;
#pragma unroll
        for (int ks = 0; ks < 4; ks++) {
            uint32_t a[4][4];
#pragma unroll
            for (int mi = 0; mi < 4; mi++) {
                uint32_t o = (aRow + mi * 16) * 128 + (2 * ks + aChk) * 16;
                ldsm4(a[mi][0], a[mi][1], a[mi][2], a[mi][3], aB + swz(o));
            }
            uint32_t bf[4][2];
#pragma unroll
            for (int j = 0; j < 2; j++) {
                uint32_t t0, t1, t2, t3;
                uint32_t o = (bRow0 + j * 16) * 128 + (2 * ks + bChk) * 16;
                ldsm4(t0, t1, t2, t3, bB_ + swz(o));
                bf[2 * j][0] = t0;     bf[2 * j][1] = t1;
                bf[2 * j + 1][0] = t2; bf[2 * j + 1][1] = t3;
            }
#pragma unroll
            for (int mi = 0; mi < 4; mi++)
#pragma unroll
                for (int nj = 0; nj < 4; nj++)
                    mma16816(acc[mi][nj], a[mi][0], a[mi][1], a[mi][2], a[mi][3],
                             bf[nj][0], bf[nj][1]);
        }
    };

    issue(stB[0], 0);
    issue(stB[1], 1);
    auto step = [&](int kc, int st) {
        asm volatile("cp.async.wait_group 1;");
        __syncthreads();
        compute(stB[st]);
        if (kc + 2 < NKC) issue(stB[(st + 2) % 3], kc + 2);
        else asm volatile("cp.async.commit_group;");
    };
#pragma unroll 1
    for (int kc = 0; kc < NKC; kc += 3) {
        step(kc, 0); step(kc + 1, 1); step(kc + 2, 2);
    }

    // epilogue
#pragma unroll
    for (int mi = 0; mi < 4; mi++) {
        int row = m0 + wm * 64 + mi * 16 + (lane >> 2);
#pragma unroll
        for (int nj = 0; nj < 4; nj++) {
            int col = n0 + wn * 32 + nj * 8 + (lane & 3) * 2;
            float* cf = acc[mi][nj];
#pragma unroll
            for (int h = 0; h < 2; h++) {
                int r = row + h * 8;
                if (r >= M) continue;
                float* p = C + (size_t)r * N + col;
#pragma unroll
                for (int q = 0; q < 2; q++) {
                    if (col + q >= N) continue;
                    float v = cf[h * 2 + q];
                    if (EPI == EPI_ACC) v += p[q];
                    if (EPI == EPI_SIG) v = 1.f / (1.f + __expf(-v));
                    p[q] = v;
                }
            }
        }
    }
}

// ---------------- merged SpMM over both graphs ----------------
__global__ void spmm2(const int* __restrict__ r1, const int* __restrict__ c1,
                      const float* __restrict__ v1, const float* __restrict__ s1,
                      float* __restrict__ a1,
                      const int* __restrict__ r2, const int* __restrict__ c2,
                      const float* __restrict__ v2, const float* __restrict__ s2,
                      float* __restrict__ a2) {
    int e = blockIdx.x * 4 + (threadIdx.x >> 6);
    int t = threadIdx.x & 63;
    const int *R, *C;
    const float *V, *S;
    float* A;
    if (e < N_EDGES) { R = r1; C = c1; V = v1; S = s1; A = a1; }
    else { e -= N_EDGES; if (e >= N_EDGES) return; R = r2; C = c2; V = v2; S = s2; A = a2; }
    int r = R[e], c = C[e];
    float v = V[e];
    float4 s = *(const float4*)(S + (size_t)c * EMB + t * 4);
    float4 a = make_float4(v * s.x, v * s.y, v * s.z, v * s.w);
    atomicAdd((float4*)(A + (size_t)r * EMB + t * 4), a);
}

// ---------------- merged node batchnorm stats (both branches) ----------------
#define NB_XR 198   // ceil(N_TOT/256)
#define NB_X  196   // ceil(N_ENTS/256)
__global__ void colstats2(const float* __restrict__ aggXR, const float* __restrict__ aggX) {
    int c = threadIdx.x;
    int b = blockIdx.x;
    const float* X;
    int r0, r1, off;
    if (b < NB_XR) { X = aggXR; r0 = b * 256; r1 = min(r0 + 256, N_TOT); off = 0; }
    else { X = aggX; r0 = (b - NB_XR) * 256; r1 = min(r0 + 256, N_ENTS); off = 256; }
    float s = 0.f, s2 = 0.f;
    for (int r = r0; r < r1; r++) {
        float v = X[(size_t)r * EMB + c];
        s += v; s2 += v * v;
    }
    atomicAdd(&g_csum[off + c], s);
    atomicAdd(&g_csq[off + c], s2);
}

__global__ void bn_final2(const float* __restrict__ g2g, const float* __restrict__ g2b,
                          const float* __restrict__ g1g, const float* __restrict__ g1b) {
    int c = threadIdx.x;   // 0..511
    float inv_n = c < 256 ? (1.f / N_TOT) : (1.f / N_ENTS);
    float gam = c < 256 ? g2g[c] : g1g[c - 256];
    float bet = c < 256 ? g2b[c] : g1b[c - 256];
    float m = g_csum[c] * inv_n;
    float var = g_csq[c] * inv_n - m * m;
    float sc = rsqrtf(var + BN_EPS) * gam;
    g_scale[c] = sc;
    g_shift[c] = bet - m * sc;
}

// ---------------- score head ----------------
__global__ void vecvec(const float* __restrict__ X, const float* __restrict__ R,
                       const int* __restrict__ e1, const int* __restrict__ ri,
                       float* __restrict__ hr) {
    int b = blockIdx.x;
    int s = threadIdx.x;
    const float* h = X + (size_t)e1[b] * EMB;
    const float* p = R + (size_t)ri[b] * EMB;
    float pr = p[s], pi = p[64 + s], pj = p[128 + s], pk = p[192 + s];
    float inv = rsqrtf(pr * pr + pi * pi + pj * pj + pk * pk);
    pr *= inv; pi *= inv; pj *= inv; pk *= inv;
    float qr = h[s], qi = h[64 + s], qj = h[128 + s], qk = h[192 + s];
    float* o = hr + (size_t)b * EMB;
    o[s]       = qr * pr - qi * pi - qj * pj - qk * pk;
    o[64 + s]  = qi * pr + qr * pi - qk * pj + qj * pk;
    o[128 + s] = qj * pr + qk * pi + qr * pj - qi * pk;
    o[192 + s] = qk * pr - qj * pi + qi * pj + qr * pk;
}

__global__ void __launch_bounds__(1024)
bn_batch(float* __restrict__ hr, const float* __restrict__ gamma,
         const float* __restrict__ beta) {
    __shared__ float ss[4][EMB], sq[4][EMB], sc[EMB], sh[EMB];
    int c = threadIdx.x & 255, g = threadIdx.x >> 8;
    float s = 0.f, s2 = 0.f;
    for (int b = g * 128; b < g * 128 + 128; b++) {
        float v = hr[(size_t)b * EMB + c];
        s += v; s2 += v * v;
    }
    ss[g][c] = s; sq[g][c] = s2;
    __syncthreads();
    if (g == 0) {
        float S = ss[0][c] + ss[1][c] + ss[2][c] + ss[3][c];
        float Q = sq[0][c] + sq[1][c] + sq[2][c] + sq[3][c];
        float m = S * (1.f / BATCH);
        float var = Q * (1.f / BATCH) - m * m;
        float scale = rsqrtf(var + BN_EPS) * gamma[c];
        sc[c] = scale; sh[c] = beta[c] - m * scale;
    }
    __syncthreads();
    float scale = sc[c], shift = sh[c];
    for (int b = g * 128; b < g * 128 + 128; b++)
        hr[(size_t)b * EMB + c] = hr[(size_t)b * EMB + c] * scale + shift;
}

// ---------------- host orchestration ----------------
static void run_score_s(int s, const int* e1, const int* ri,
                        const float* bsg, const float* bsb,
                        float* XR, float* hr, float* out,
                        __nv_bfloat16* SA1, __nv_bfloat16* hrA, cudaStream_t st) {
    vecvec<<<BATCH, 64, 0, st>>>(XR, XR + (size_t)N_ENTS * EMB, e1, ri, hr);
    bn_batch<<<1, 1024, 0, st>>>(hr, bsg + s * EMB, bsb + s * EMB);
    split_hl<<<(BATCH * 64 + 255) / 256, 256, 0, st>>>(hr, hrA, BATCH * 64);
    dim3 g((N_ENTS + BN - 1) / BN, (BATCH + BM - 1) / BM);   // (391, 4)
    gemm_bf16<EPI_SIG><<<g, 256, SM_GEMM, st>>>(hrA, SA1,
                                                out + (size_t)s * BATCH * N_ENTS,
                                                BATCH, N_ENTS);
}

extern "C" void kernel_launch(void* const* d_in, const int* in_sizes, int n_in,
                              void* d_out, int out_size) {
    const int*   e1      = (const int*)d_in[0];
    const int*   ri      = (const int*)d_in[1];
    const float* emb     = (const float*)d_in[2];
    const float* gcn1_w  = (const float*)d_in[3];
    const float* gcn2_w  = (const float*)d_in[4];
    const float* g1_gam  = (const float*)d_in[5];
    const float* g1_bet  = (const float*)d_in[6];
    const float* g2_gam  = (const float*)d_in[7];
    const float* g2_bet  = (const float*)d_in[8];
    const float* lin     = (const float*)d_in[9];
    const float* bsg     = (const float*)d_in[10];
    const float* bsb     = (const float*)d_in[11];
    const int*   a_rows  = (const int*)d_in[12];
    const int*   a_cols  = (const int*)d_in[13];
    const float* a_vals  = (const float*)d_in[14];
    const int*   ar_rows = (const int*)d_in[15];
    const int*   ar_cols = (const int*)d_in[16];
    const float* ar_vals = (const float*)d_in[17];
    float* out = (float*)d_out;

    cudaFuncSetAttribute(gemm_bf16<EPI_STORE>, cudaFuncAttributeMaxDynamicSharedMemorySize, SM_GEMM);
    cudaFuncSetAttribute(gemm_bf16<EPI_ACC>,   cudaFuncAttributeMaxDynamicSharedMemorySize, SM_GEMM);
    cudaFuncSetAttribute(gemm_bf16<EPI_SIG>,   cudaFuncAttributeMaxDynamicSharedMemorySize, SM_GEMM);

    // side stream + events (host resources, created once; no device memory)
    static cudaStream_t s_side = nullptr;
    static cudaEvent_t evA[2], evV[2], evS[2];
    if (!s_side) {
        cudaStreamCreateWithFlags(&s_side, cudaStreamNonBlocking);
        for (int i = 0; i < 2; i++) {
            cudaEventCreateWithFlags(&evA[i], cudaEventDisableTiming);
            cudaEventCreateWithFlags(&evV[i], cudaEventDisableTiming);
            cudaEventCreateWithFlags(&evS[i], cudaEventDisableTiming);
        }
    }

    float *XR, *sup, *supX, *agg, *aggX, *hr, *HamT, *H1T, *H2T, *csum, *csq;
    __nv_bfloat16 *SA1, *SA2, *SA3, *Wb, *Wb2, *hrA;
    cudaGetSymbolAddress((void**)&XR,   g_XR);
    cudaGetSymbolAddress((void**)&sup,  g_sup);
    cudaGetSymbolAddress((void**)&supX, g_supX);
    cudaGetSymbolAddress((void**)&agg,  g_agg);
    cudaGetSymbolAddress((void**)&aggX, g_aggX);
    cudaGetSymbolAddress((void**)&hr,   g_hr);
    cudaGetSymbolAddress((void**)&HamT, g_HamT);
    cudaGetSymbolAddress((void**)&H1T,  g_H1T);
    cudaGetSymbolAddress((void**)&H2T,  g_H2T);
    cudaGetSymbolAddress((void**)&csum, g_csum);
    cudaGetSymbolAddress((void**)&csq,  g_csq);
    cudaGetSymbolAddress((void**)&SA1,  g_SA1);
    cudaGetSymbolAddress((void**)&SA2,  g_SA2);
    cudaGetSymbolAddress((void**)&SA3,  g_SA3);
    cudaGetSymbolAddress((void**)&Wb,   g_Wb);
    cudaGetSymbolAddress((void**)&Wb2,  g_Wb2);
    cudaGetSymbolAddress((void**)&hrA,  g_hrA);

    cudaMemcpyAsync(XR, emb, (size_t)N_TOT * EMB * sizeof(float),
                    cudaMemcpyDeviceToDevice);

    const dim3 gW(EMB / BN, (N_TOT + BM - 1) / BM);     // (2, 395)
    const dim3 gWe(EMB / BN, (N_ENTS + BM - 1) / BM);   // (2, 391)
    const int BLK_TOT = (N_TOT * 64 + 255) / 256;
    const int BLK_ENT = (N_ENTS * 64 + 255) / 256;
    const int BLK_EMB = (EMB * 64 + 255) / 256;

    // prologue — keeps a real GEMM at launch #4 for ncu
    build_hamT<<<(EMB * EMB + 255) / 256, 256>>>(gcn2_w, HamT);        // #1
    split_hl<<<BLK_EMB, 256>>>(HamT, Wb, EMB * 64);                    // #2
    split_hl<<<BLK_TOT, 256>>>(XR, SA1, N_TOT * 64);                   // #3
    cudaEventRecord(evA[0], 0);   // XR + SA1 ready for score 0

    for (int l = 0; l < 2; l++) {
        // ---- main: both branch sup GEMMs ----
        if (l > 0) {
            build_hamT<<<(EMB * EMB + 255) / 256, 256>>>(gcn2_w + (size_t)l * 64 * EMB, HamT);
            split_hl<<<BLK_EMB, 256>>>(HamT, Wb, EMB * 64);
        }
        gemm_bf16<EPI_STORE><<<gW, 256, SM_GEMM>>>(SA1, Wb, sup, N_TOT, EMB);   // #4 at l=0
        build_hamT<<<(EMB * EMB + 255) / 256, 256>>>(gcn1_w + (size_t)l * 64 * EMB, H1T);
        split_hl<<<BLK_EMB, 256>>>(H1T, Wb2, EMB * 64);
        gemm_bf16<EPI_STORE><<<gWe, 256, SM_GEMM>>>(SA1, Wb2, supX, N_ENTS, EMB);

        // ---- side: score(l) overlapped with the spmm/bn chain ----
        cudaStreamWaitEvent(s_side, evA[l], 0);
        vecvec<<<BATCH, 64, 0, s_side>>>(XR, XR + (size_t)N_ENTS * EMB, e1, ri, hr);
        cudaEventRecord(evV[l], s_side);              // XR no longer read by side
        bn_batch<<<1, 1024, 0, s_side>>>(hr, bsg + l * EMB, bsb + l * EMB);
        split_hl<<<(BATCH * 64 + 255) / 256, 256, 0, s_side>>>(hr, hrA, BATCH * 64);
        {
            dim3 g((N_ENTS + BN - 1) / BN, (BATCH + BM - 1) / BM);
            gemm_bf16<EPI_SIG><<<g, 256, SM_GEMM, s_side>>>(
                hrA, SA1, out + (size_t)l * BATCH * N_ENTS, BATCH, N_ENTS);
        }
        cudaEventRecord(evS[l], s_side);              // SA1 no longer read by side

        // ---- main: merged segment-sum + stats ----
        cudaMemsetAsync(agg,  0, (size_t)N_TOT * EMB * sizeof(float));
        cudaMemsetAsync(aggX, 0, (size_t)N_ENTS * EMB * sizeof(float));
        spmm2<<<(2 * N_EDGES + 3) / 4, 256>>>(ar_rows, ar_cols, ar_vals, sup, agg,
                                              a_rows, a_cols, a_vals, supX, aggX);
        cudaMemsetAsync(csum, 0, 2 * EMB * sizeof(float));
        cudaMemsetAsync(csq,  0, 2 * EMB * sizeof(float));
        colstats2<<<NB_XR + NB_X, EMB>>>(agg, aggX);
        bn_final2<<<1, 2 * EMB>>>(g2_gam + l * EMB, g2_bet + l * EMB,
                                  g1_gam + l * EMB, g1_bet + l * EMB);
        cudaStreamWaitEvent(0, evV[l], 0);            // side done reading XR
        bn_tanh_split<true><<<BLK_TOT, 256>>>(agg, XR, SA2, 0, N_TOT * 64);
        bn_tanh_split<false><<<BLK_ENT, 256>>>(aggX, nullptr, SA3, 256, N_ENTS * 64);

        // ---- main: lin: X_new = Xef @ H1^T + Xrf @ H2^T ----
        build_hamLPT<<<EMB, EMB>>>(lin + (size_t)l * 128 * EMB, H1T, H2T);
        split_hl<<<BLK_EMB, 256>>>(H1T, Wb, EMB * 64);
        split_hl<<<BLK_EMB, 256>>>(H2T, Wb2, EMB * 64);
        gemm_bf16<EPI_STORE><<<gWe, 256, SM_GEMM>>>(SA3, Wb, XR, N_ENTS, EMB);
        gemm_bf16<EPI_ACC><<<gWe, 256, SM_GEMM>>>(SA2, Wb2, XR, N_ENTS, EMB);

        cudaStreamWaitEvent(0, evS[l], 0);            // side done reading SA1 (joins side)
        split_hl<<<BLK_TOT, 256>>>(XR, SA1, N_TOT * 64);
        if (l == 0) cudaEventRecord(evA[1], 0);       // ready for score 1
    }

    // final score on main (terminal, nothing to overlap)
    run_score_s(2, e1, ri, bsg, bsb, XR, hr, out, SA1, hrA, 0);
}

// round 10
// speedup vs baseline: 1.3171x; 1.0924x over previous
#include <cuda_runtime.h>
#include <cuda_bf16.h>
#include <stdint.h>

#define N_ENTS 50000
#define N_RELS 500
#define N_TOT  50500
#define EMB    256
#define N_EDGES 400000
#define BATCH  512
#define BN_EPS 1e-5f
#define KS2    512   // h|l storage width (bf16x3 streams 768 via chunk tables)

// ---------------- scratch (__device__ globals, no allocations) ----------------
__device__ float g_XR[(size_t)N_TOT * EMB];
__device__ float g_supC[(size_t)N_TOT * 2 * EMB];   // fused support: cols 0-255 XR-branch, 256-511 X-branch
__device__ float g_agg[(size_t)N_TOT * EMB];        // XR-branch segment sum
__device__ float g_aggX[(size_t)N_ENTS * EMB];      // X-branch segment sum
__device__ float g_hr[(size_t)BATCH * EMB];
__device__ float g_csum[2 * EMB];
__device__ float g_csq[2 * EMB];
__device__ float g_scale[2 * EMB];
__device__ float g_shift[2 * EMB];

// h|l split buffers: [n, 512] bf16, cols 0-255 = hi, 256-511 = lo
__device__ __nv_bfloat16 g_SA1[(size_t)N_TOT * KS2];     // split of XR
__device__ __nv_bfloat16 g_SA2[(size_t)N_TOT * KS2];     // split of XRrf
__device__ __nv_bfloat16 g_SA3[(size_t)N_ENTS * KS2];    // split of Xef
__device__ __nv_bfloat16 g_WbC[512 * KS2];               // fused gcn weights (512 out cols)
__device__ __nv_bfloat16 g_Wb[EMB * KS2];                // lin weights H1
__device__ __nv_bfloat16 g_Wb2[EMB * KS2];               // lin weights H2
__device__ __nv_bfloat16 g_hrA[(size_t)BATCH * KS2];     // split hr

// quaternion block tables
__constant__ int   c_comp[4][4] = {{0,1,2,3},{1,0,3,2},{2,3,0,1},{3,2,1,0}};
__constant__ float c_sign[4][4] = {{ 1.f, 1.f, 1.f, 1.f},
                                   {-1.f, 1.f, 1.f,-1.f},
                                   {-1.f,-1.f, 1.f, 1.f},
                                   {-1.f, 1.f,-1.f, 1.f}};

// bf16x3 chunk schedule (64-half chunks): AhBh x4, AlBh x4, AhBl x4
__constant__ int c_ka[12] = {0,64,128,192, 256,320,384,448, 0,64,128,192};
__constant__ int c_kb[12] = {0,64,128,192, 0,64,128,192, 256,320,384,448};

// ---------------- helpers ----------------
static __device__ __forceinline__ void split1(float x, __nv_bfloat16& h, __nv_bfloat16& l) {
    h = __float2bfloat16(x);
    l = __float2bfloat16(x - __bfloat162float(h));
}
static __device__ __forceinline__ uint2 pack4(__nv_bfloat16 a, __nv_bfloat16 b,
                                              __nv_bfloat16 c, __nv_bfloat16 d) {
    uint2 u;
    u.x = ((uint32_t)__bfloat16_as_ushort(b) << 16) | __bfloat16_as_ushort(a);
    u.y = ((uint32_t)__bfloat16_as_ushort(d) << 16) | __bfloat16_as_ushort(c);
    return u;
}

// ---------------- fused hamilton build + h|l split ----------------
// gcn ham (W 64x256): out rows [off, off+256) of WbC[512, KS2]
__global__ void build_ham_split(const float* __restrict__ W, __nv_bfloat16* __restrict__ out,
                                int off) {
    int idx = blockIdx.x * blockDim.x + threadIdx.x;
    if (idx >= EMB * EMB) return;
    int c = idx >> 8, k = idx & 255;
    int a = k >> 6, u = k & 63, b = c >> 6, v = c & 63;
    float val = c_sign[a][b] * W[u * EMB + c_comp[a][b] * 64 + v];
    __nv_bfloat16 h, l;
    split1(val, h, l);
    size_t base = (size_t)(off + c) * KS2;
    out[base + k] = h;
    out[base + 256 + k] = l;
}

// lin ham (W 128x256) with Xcat permutation folded: writes H1->Wb, H2->Wb2 (split)
__global__ void build_lin_split(const float* __restrict__ W, __nv_bfloat16* __restrict__ o1,
                                __nv_bfloat16* __restrict__ o2) {
    int c = blockIdx.x, j = threadIdx.x;
    int q = j >> 6, s = j & 63;
    int b = c >> 6, v = c & 63;
    int pe = 128 * q + s;
    int pr = pe + 64;
    int a1 = pe >> 7, u1 = pe & 127;
    int a2 = pr >> 7, u2 = pr & 127;
    float v1 = c_sign[a1][b] * W[u1 * EMB + c_comp[a1][b] * 64 + v];
    float v2 = c_sign[a2][b] * W[u2 * EMB + c_comp[a2][b] * 64 + v];
    __nv_bfloat16 h, l;
    size_t base = (size_t)c * KS2;
    split1(v1, h, l); o1[base + j] = h; o1[base + 256 + j] = l;
    split1(v2, h, l); o2[base + j] = h; o2[base + 256 + j] = l;
}

// ---------------- h|l split conversion ----------------
__global__ void split_hl(const float* __restrict__ in, __nv_bfloat16* __restrict__ out,
                         int n64) {
    int i = blockIdx.x * blockDim.x + threadIdx.x;
    if (i >= n64) return;
    int r = i >> 6, c4 = (i & 63) << 2;
    float4 x = *(const float4*)(in + (size_t)r * EMB + c4);
    __nv_bfloat16 h[4], l[4];
    split1(x.x, h[0], l[0]); split1(x.y, h[1], l[1]);
    split1(x.z, h[2], l[2]); split1(x.w, h[3], l[3]);
    size_t b = (size_t)r * KS2 + c4;
    *(uint2*)(out + b) = pack4(h[0], h[1], h[2], h[3]);
    *(uint2*)(out + b + 256) = pack4(l[0], l[1], l[2], l[3]);
}

// bn+tanh fused with h|l split output.
// WRR: write float rows >= N_ENTS into XRout (the R-row update)
template <bool WRR>
__global__ void bn_tanh_split(const float* __restrict__ X, float* __restrict__ XRout,
                              __nv_bfloat16* __restrict__ out, int so, int n64) {
    int i = blockIdx.x * blockDim.x + threadIdx.x;
    if (i >= n64) return;
    int r = i >> 6, c4 = (i & 63) << 2;
    float4 x = *(const float4*)(X + (size_t)r * EMB + c4);
    float y[4];
    float* xs = &x.x;
#pragma unroll
    for (int j = 0; j < 4; j++) {
        float z = xs[j] * g_scale[so + c4 + j] + g_shift[so + c4 + j];
        float e = __expf(-2.f * fabsf(z));
        float t = (1.f - e) / (1.f + e);
        y[j] = copysignf(t, z);
    }
    if (WRR && r >= N_ENTS)
        *(float4*)(XRout + (size_t)r * EMB + c4) = make_float4(y[0], y[1], y[2], y[3]);
    __nv_bfloat16 h[4], l[4];
#pragma unroll
    for (int j = 0; j < 4; j++) split1(y[j], h[j], l[j]);
    size_t b = (size_t)r * KS2 + c4;
    *(uint2*)(out + b) = pack4(h[0], h[1], h[2], h[3]);
    *(uint2*)(out + b + 256) = pack4(l[0], l[1], l[2], l[3]);
}

// ====== bf16 HMMA GEMM: 128x128 tile, 64x32 warps, 3-stage, 2 CTA/SM ======
// DUAL: 24 chunks — 0-11 from (A,B), 12-23 from (A+dA, B+dB); accumulates both products.
enum { EPI_STORE = 0, EPI_SIG = 2 };

#define BM 128
#define BN 128
#define STAGE_SZ 32768            // A 16KB + B 16KB
#define SM_GEMM (3 * STAGE_SZ)    // 98304

static __device__ __forceinline__ uint32_t cvtas(const void* p) {
    uint32_t a;
    asm("{ .reg .u64 t; cvta.to.shared.u64 t, %1; cvt.u32.u64 %0, t; }" : "=r"(a) : "l"(p));
    return a;
}
static __device__ __forceinline__ uint32_t swz(uint32_t o) { return o ^ ((o >> 3) & 0x70); }
static __device__ __forceinline__ void cp16(uint32_t d, const void* g, int sz) {
    asm volatile("cp.async.cg.shared.global [%0], [%1], 16, %2;" :: "r"(d), "l"(g), "r"(sz));
}
static __device__ __forceinline__ void ldsm4(uint32_t& d0, uint32_t& d1, uint32_t& d2,
                                             uint32_t& d3, uint32_t a) {
    asm volatile("ldmatrix.sync.aligned.m8n8.x4.shared.b16 {%0,%1,%2,%3}, [%4];"
                 : "=r"(d0), "=r"(d1), "=r"(d2), "=r"(d3) : "r"(a));
}
static __device__ __forceinline__ void mma16816(float* c, uint32_t a0, uint32_t a1,
                                                uint32_t a2, uint32_t a3,
                                                uint32_t b0, uint32_t b1) {
    asm volatile("mma.sync.aligned.m16n8k16.row.col.f32.bf16.bf16.f32 "
                 "{%0,%1,%2,%3}, {%4,%5,%6,%7}, {%8,%9}, {%0,%1,%2,%3};"
                 : "+f"(c[0]), "+f"(c[1]), "+f"(c[2]), "+f"(c[3])
                 : "r"(a0), "r"(a1), "r"(a2), "r"(a3), "r"(b0), "r"(b1));
}

template <int EPI, bool DUAL>
__global__ void __launch_bounds__(256, 2)
gemm_bf16(const __nv_bfloat16* __restrict__ A, const __nv_bfloat16* __restrict__ B,
          const __nv_bfloat16* __restrict__ A2, const __nv_bfloat16* __restrict__ B2,
          float* __restrict__ C, int M, int N) {
    extern __shared__ char smem[];
    const uint32_t sb = cvtas(smem);
    const uint32_t stB[3] = { sb, sb + STAGE_SZ, sb + 2 * STAGE_SZ };
    const int NKC = DUAL ? 24 : 12;

    const int tid = threadIdx.x;
    const int lane = tid & 31, wid = tid >> 5;
    const int wm = wid >> 2, wn = wid & 3;
    const int m0 = blockIdx.y * BM, n0 = blockIdx.x * BN;

    const int r0 = tid >> 2;
    const int c2 = (tid & 3) * 2;
    uint32_t soff[2][2];
#pragma unroll
    for (int r = 0; r < 2; r++)
#pragma unroll
        for (int q = 0; q < 2; q++)
            soff[r][q] = swz((uint32_t)(r0 + r * 64) * 128 + (uint32_t)(c2 + q) * 16);

    int szA[2], szB[2];
    const __nv_bfloat16 *Ag[2], *Bg[2];
#pragma unroll
    for (int r = 0; r < 2; r++) {
        long mr = m0 + r0 + r * 64, nr = n0 + r0 + r * 64;
        szA[r] = mr < M ? 16 : 0;
        szB[r] = nr < N ? 16 : 0;
        Ag[r] = A + (size_t)(mr < M ? mr : M - 1) * KS2 + c2 * 8;
        Bg[r] = B + (size_t)(nr < N ? nr : N - 1) * KS2 + c2 * 8;
    }
    // uniform deltas for the second pass (DUAL only)
    const ptrdiff_t dA = DUAL ? (A2 - A) : 0;
    const ptrdiff_t dB = DUAL ? (B2 - B) : 0;

    float acc[4][4][4];
#pragma unroll
    for (int i = 0; i < 4; i++)
#pragma unroll
        for (int j = 0; j < 4; j++)
#pragma unroll
            for (int q = 0; q < 4; q++) acc[i][j][q] = 0.f;

    auto issue = [&](uint32_t stBase, int kc) {
        const bool p2 = DUAL && (kc >= 12);
        const int kcm = p2 ? kc - 12 : kc;
        const int ka = c_ka[kcm], kb = c_kb[kcm];
        const ptrdiff_t oa = p2 ? dA : 0, ob = p2 ? dB : 0;
        const uint32_t aB = stBase, bB_ = stBase + 16384;
#pragma unroll
        for (int q = 0; q < 2; q++)
#pragma unroll
            for (int r = 0; r < 2; r++) {
                cp16(aB + soff[r][q], Ag[r] + oa + ka + q * 8, szA[r]);
                cp16(bB_ + soff[r][q], Bg[r] + ob + kb + q * 8, szB[r]);
            }
        asm volatile("cp.async.commit_group;");
    };

    const uint32_t aRow = (uint32_t)(wm * 64 + (lane & 15));
    const uint32_t aChk = (uint32_t)(lane >> 4);
    const uint32_t bRow0 = (uint32_t)(wn * 32 + (lane & 7) + ((lane >> 4) & 1) * 8);
    const uint32_t bChk = (uint32_t)((lane >> 3) & 1);

    auto compute = [&](uint32_t stBase) {
        const uint32_t aB = stBase, bB_ = stBase + 16384;
#pragma unroll
        for (int ks = 0; ks < 4; ks++) {
            uint32_t a[4][4];
#pragma unroll
            for (int mi = 0; mi < 4; mi++) {
                uint32_t o = (aRow + mi * 16) * 128 + (2 * ks + aChk) * 16;
                ldsm4(a[mi][0], a[mi][1], a[mi][2], a[mi][3], aB + swz(o));
            }
            uint32_t bf[4][2];
#pragma unroll
            for (int j = 0; j < 2; j++) {
                uint32_t t0, t1, t2, t3;
                uint32_t o = (bRow0 + j * 16) * 128 + (2 * ks + bChk) * 16;
                ldsm4(t0, t1, t2, t3, bB_ + swz(o));
                bf[2 * j][0] = t0;     bf[2 * j][1] = t1;
                bf[2 * j + 1][0] = t2; bf[2 * j + 1][1] = t3;
            }
#pragma unroll
            for (int mi = 0; mi < 4; mi++)
#pragma unroll
                for (int nj = 0; nj < 4; nj++)
                    mma16816(acc[mi][nj], a[mi][0], a[mi][1], a[mi][2], a[mi][3],
                             bf[nj][0], bf[nj][1]);
        }
    };

    issue(stB[0], 0);
    issue(stB[1], 1);
    auto step = [&](int kc, int st) {
        asm volatile("cp.async.wait_group 1;");
        __syncthreads();
        compute(stB[st]);
        if (kc + 2 < NKC) issue(stB[(st + 2) % 3], kc + 2);
        else asm volatile("cp.async.commit_group;");
    };
#pragma unroll 1
    for (int kc = 0; kc < NKC; kc += 3) {
        step(kc, 0); step(kc + 1, 1); step(kc + 2, 2);
    }

    // epilogue
#pragma unroll
    for (int mi = 0; mi < 4; mi++) {
        int row = m0 + wm * 64 + mi * 16 + (lane >> 2);
#pragma unroll
        for (int nj = 0; nj < 4; nj++) {
            int col = n0 + wn * 32 + nj * 8 + (lane & 3) * 2;
            float* cf = acc[mi][nj];
#pragma unroll
            for (int h = 0; h < 2; h++) {
                int r = row + h * 8;
                if (r >= M) continue;
                float* p = C + (size_t)r * N + col;
#pragma unroll
                for (int q = 0; q < 2; q++) {
                    if (col + q >= N) continue;
                    float v = cf[h * 2 + q];
                    if (EPI == EPI_SIG) v = 1.f / (1.f + __expf(-v));
                    p[q] = v;
                }
            }
        }
    }
}

// ---------------- merged SpMM over both graphs (sup row stride = 512) ----------------
__global__ void spmm2(const int* __restrict__ r1, const int* __restrict__ c1,
                      const float* __restrict__ v1, const float* __restrict__ s1,
                      float* __restrict__ a1,
                      const int* __restrict__ r2, const int* __restrict__ c2,
                      const float* __restrict__ v2, const float* __restrict__ s2,
                      float* __restrict__ a2) {
    int e = blockIdx.x * 4 + (threadIdx.x >> 6);
    int t = threadIdx.x & 63;
    const int *R, *C;
    const float *V, *S;
    float* A;
    if (e < N_EDGES) { R = r1; C = c1; V = v1; S = s1; A = a1; }
    else { e -= N_EDGES; if (e >= N_EDGES) return; R = r2; C = c2; V = v2; S = s2; A = a2; }
    int r = R[e], c = C[e];
    float v = V[e];
    float4 s = *(const float4*)(S + (size_t)c * 512 + t * 4);
    float4 a = make_float4(v * s.x, v * s.y, v * s.z, v * s.w);
    atomicAdd((float4*)(A + (size_t)r * EMB + t * 4), a);
}

// ---------------- merged node batchnorm stats (both branches) ----------------
#define NB_XR 198   // ceil(N_TOT/256)
#define NB_X  196   // ceil(N_ENTS/256)
__global__ void colstats2(const float* __restrict__ aggXR, const float* __restrict__ aggX) {
    int c = threadIdx.x;
    int b = blockIdx.x;
    const float* X;
    int r0, r1, off;
    if (b < NB_XR) { X = aggXR; r0 = b * 256; r1 = min(r0 + 256, N_TOT); off = 0; }
    else { X = aggX; r0 = (b - NB_XR) * 256; r1 = min(r0 + 256, N_ENTS); off = 256; }
    float s = 0.f, s2 = 0.f;
    for (int r = r0; r < r1; r++) {
        float v = X[(size_t)r * EMB + c];
        s += v; s2 += v * v;
    }
    atomicAdd(&g_csum[off + c], s);
    atomicAdd(&g_csq[off + c], s2);
}

__global__ void bn_final2(const float* __restrict__ g2g, const float* __restrict__ g2b,
                          const float* __restrict__ g1g, const float* __restrict__ g1b) {
    int c = threadIdx.x;   // 0..511
    float inv_n = c < 256 ? (1.f / N_TOT) : (1.f / N_ENTS);
    float gam = c < 256 ? g2g[c] : g1g[c - 256];
    float bet = c < 256 ? g2b[c] : g1b[c - 256];
    float m = g_csum[c] * inv_n;
    float var = g_csq[c] * inv_n - m * m;
    float sc = rsqrtf(var + BN_EPS) * gam;
    g_scale[c] = sc;
    g_shift[c] = bet - m * sc;
}

// ---------------- score head ----------------
__global__ void vecvec(const float* __restrict__ X, const float* __restrict__ R,
                       const int* __restrict__ e1, const int* __restrict__ ri,
                       float* __restrict__ hr) {
    int b = blockIdx.x;
    int s = threadIdx.x;
    const float* h = X + (size_t)e1[b] * EMB;
    const float* p = R + (size_t)ri[b] * EMB;
    float pr = p[s], pi = p[64 + s], pj = p[128 + s], pk = p[192 + s];
    float inv = rsqrtf(pr * pr + pi * pi + pj * pj + pk * pk);
    pr *= inv; pi *= inv; pj *= inv; pk *= inv;
    float qr = h[s], qi = h[64 + s], qj = h[128 + s], qk = h[192 + s];
    float* o = hr + (size_t)b * EMB;
    o[s]       = qr * pr - qi * pi - qj * pj - qk * pk;
    o[64 + s]  = qi * pr + qr * pi - qk * pj + qj * pk;
    o[128 + s] = qj * pr + qk * pi + qr * pj - qi * pk;
    o[192 + s] = qk * pr - qj * pi + qi * pj + qr * pk;
}

__global__ void __launch_bounds__(1024)
bn_batch(float* __restrict__ hr, const float* __restrict__ gamma,
         const float* __restrict__ beta) {
    __shared__ float ss[4][EMB], sq[4][EMB], sc[EMB], sh[EMB];
    int c = threadIdx.x & 255, g = threadIdx.x >> 8;
    float s = 0.f, s2 = 0.f;
    for (int b = g * 128; b < g * 128 + 128; b++) {
        float v = hr[(size_t)b * EMB + c];
        s += v; s2 += v * v;
    }
    ss[g][c] = s; sq[g][c] = s2;
    __syncthreads();
    if (g == 0) {
        float S = ss[0][c] + ss[1][c] + ss[2][c] + ss[3][c];
        float Q = sq[0][c] + sq[1][c] + sq[2][c] + sq[3][c];
        float m = S * (1.f / BATCH);
        float var = Q * (1.f / BATCH) - m * m;
        float scale = rsqrtf(var + BN_EPS) * gamma[c];
        sc[c] = scale; sh[c] = beta[c] - m * scale;
    }
    __syncthreads();
    float scale = sc[c], shift = sh[c];
    for (int b = g * 128; b < g * 128 + 128; b++)
        hr[(size_t)b * EMB + c] = hr[(size_t)b * EMB + c] * scale + shift;
}

// ---------------- host orchestration ----------------
extern "C" void kernel_launch(void* const* d_in, const int* in_sizes, int n_in,
                              void* d_out, int out_size) {
    const int*   e1      = (const int*)d_in[0];
    const int*   ri      = (const int*)d_in[1];
    const float* emb     = (const float*)d_in[2];
    const float* gcn1_w  = (const float*)d_in[3];
    const float* gcn2_w  = (const float*)d_in[4];
    const float* g1_gam  = (const float*)d_in[5];
    const float* g1_bet  = (const float*)d_in[6];
    const float* g2_gam  = (const float*)d_in[7];
    const float* g2_bet  = (const float*)d_in[8];
    const float* lin     = (const float*)d_in[9];
    const float* bsg     = (const float*)d_in[10];
    const float* bsb     = (const float*)d_in[11];
    const int*   a_rows  = (const int*)d_in[12];
    const int*   a_cols  = (const int*)d_in[13];
    const float* a_vals  = (const float*)d_in[14];
    const int*   ar_rows = (const int*)d_in[15];
    const int*   ar_cols = (const int*)d_in[16];
    const float* ar_vals = (const float*)d_in[17];
    float* out = (float*)d_out;

    cudaFuncSetAttribute(gemm_bf16<EPI_STORE, false>, cudaFuncAttributeMaxDynamicSharedMemorySize, SM_GEMM);
    cudaFuncSetAttribute(gemm_bf16<EPI_STORE, true>,  cudaFuncAttributeMaxDynamicSharedMemorySize, SM_GEMM);
    cudaFuncSetAttribute(gemm_bf16<EPI_SIG, false>,   cudaFuncAttributeMaxDynamicSharedMemorySize, SM_GEMM);

    static cudaStream_t s_side = nullptr;
    static cudaEvent_t evA[2], evV[2], evS[2];
    if (!s_side) {
        cudaStreamCreateWithFlags(&s_side, cudaStreamNonBlocking);
        for (int i = 0; i < 2; i++) {
            cudaEventCreateWithFlags(&evA[i], cudaEventDisableTiming);
            cudaEventCreateWithFlags(&evV[i], cudaEventDisableTiming);
            cudaEventCreateWithFlags(&evS[i], cudaEventDisableTiming);
        }
    }

    float *XR, *supC, *agg, *aggX, *hr, *csum, *csq;
    __nv_bfloat16 *SA1, *SA2, *SA3, *WbC, *Wb, *Wb2, *hrA;
    cudaGetSymbolAddress((void**)&XR,   g_XR);
    cudaGetSymbolAddress((void**)&supC, g_supC);
    cudaGetSymbolAddress((void**)&agg,  g_agg);
    cudaGetSymbolAddress((void**)&aggX, g_aggX);
    cudaGetSymbolAddress((void**)&hr,   g_hr);
    cudaGetSymbolAddress((void**)&csum, g_csum);
    cudaGetSymbolAddress((void**)&csq,  g_csq);
    cudaGetSymbolAddress((void**)&SA1,  g_SA1);
    cudaGetSymbolAddress((void**)&SA2,  g_SA2);
    cudaGetSymbolAddress((void**)&SA3,  g_SA3);
    cudaGetSymbolAddress((void**)&WbC,  g_WbC);
    cudaGetSymbolAddress((void**)&Wb,   g_Wb);
    cudaGetSymbolAddress((void**)&Wb2,  g_Wb2);
    cudaGetSymbolAddress((void**)&hrA,  g_hrA);

    cudaMemcpyAsync(XR, emb, (size_t)N_TOT * EMB * sizeof(float),
                    cudaMemcpyDeviceToDevice);

    const dim3 gWC(4, (N_TOT + BM - 1) / BM);       // fused sup GEMM: N=512
    const dim3 gWe(2, (N_ENTS + BM - 1) / BM);      // lin GEMM: N=256
    const dim3 gS((N_ENTS + BN - 1) / BN, (BATCH + BM - 1) / BM);
    const int BLK_TOT = (N_TOT * 64 + 255) / 256;
    const int BLK_ENT = (N_ENTS * 64 + 255) / 256;
    const int BLK_HAM = (EMB * EMB + 255) / 256;

    // prologue — gemm at launch #4 for ncu
    split_hl<<<BLK_TOT, 256>>>(XR, SA1, N_TOT * 64);                             // #1
    cudaEventRecord(evA[0], 0);   // XR + SA1 ready for score 0
    build_ham_split<<<BLK_HAM, 256>>>(gcn2_w, WbC, 0);                           // #2
    build_ham_split<<<BLK_HAM, 256>>>(gcn1_w, WbC, 256);                         // #3

    for (int l = 0; l < 2; l++) {
        // ---- main: fused sup GEMM (both branches, N=512) ----
        if (l > 0) {
            build_ham_split<<<BLK_HAM, 256>>>(gcn2_w + (size_t)l * 64 * EMB, WbC, 0);
            build_ham_split<<<BLK_HAM, 256>>>(gcn1_w + (size_t)l * 64 * EMB, WbC, 256);
        }
        gemm_bf16<EPI_STORE, false><<<gWC, 256, SM_GEMM>>>(SA1, WbC, nullptr, nullptr,
                                                           supC, N_TOT, 512);   // #4 at l=0

        // ---- side: score(l) overlapped with the spmm/bn chain ----
        cudaStreamWaitEvent(s_side, evA[l], 0);
        vecvec<<<BATCH, 64, 0, s_side>>>(XR, XR + (size_t)N_ENTS * EMB, e1, ri, hr);
        cudaEventRecord(evV[l], s_side);              // XR no longer read by side
        bn_batch<<<1, 1024, 0, s_side>>>(hr, bsg + l * EMB, bsb + l * EMB);
        split_hl<<<(BATCH * 64 + 255) / 256, 256, 0, s_side>>>(hr, hrA, BATCH * 64);
        gemm_bf16<EPI_SIG, false><<<gS, 256, SM_GEMM, s_side>>>(
            hrA, SA1, nullptr, nullptr, out + (size_t)l * BATCH * N_ENTS, BATCH, N_ENTS);
        cudaEventRecord(evS[l], s_side);              // SA1 no longer read by side

        // ---- main: merged segment-sum + stats ----
        cudaMemsetAsync(agg,  0, (size_t)N_TOT * EMB * sizeof(float));
        cudaMemsetAsync(aggX, 0, (size_t)N_ENTS * EMB * sizeof(float));
        spmm2<<<(2 * N_EDGES + 3) / 4, 256>>>(ar_rows, ar_cols, ar_vals, supC, agg,
                                              a_rows, a_cols, a_vals, supC + 256, aggX);
        cudaMemsetAsync(csum, 0, 2 * EMB * sizeof(float));
        cudaMemsetAsync(csq,  0, 2 * EMB * sizeof(float));
        colstats2<<<NB_XR + NB_X, EMB>>>(agg, aggX);
        bn_final2<<<1, 2 * EMB>>>(g2_gam + l * EMB, g2_bet + l * EMB,
                                  g1_gam + l * EMB, g1_bet + l * EMB);
        cudaStreamWaitEvent(0, evV[l], 0);            // side done reading XR
        bn_tanh_split<true><<<BLK_TOT, 256>>>(agg, XR, SA2, 0, N_TOT * 64);
        bn_tanh_split<false><<<BLK_ENT, 256>>>(aggX, nullptr, SA3, 256, N_ENTS * 64);

        // ---- main: fused lin: X_new = Xef @ H1^T + Xrf @ H2^T (24-chunk dual) ----
        build_lin_split<<<EMB, EMB>>>(lin + (size_t)l * 128 * EMB, Wb, Wb2);
        gemm_bf16<EPI_STORE, true><<<gWe, 256, SM_GEMM>>>(SA3, Wb, SA2, Wb2,
                                                          XR, N_ENTS, EMB);

        cudaStreamWaitEvent(0, evS[l], 0);            // side done reading SA1 (joins side)
        split_hl<<<BLK_TOT, 256>>>(XR, SA1, N_TOT * 64);
        if (l == 0) cudaEventRecord(evA[1], 0);       // ready for score 1
    }

    // final score on main (terminal)
    vecvec<<<BATCH, 64>>>(XR, XR + (size_t)N_ENTS * EMB, e1, ri, hr);
    bn_batch<<<1, 1024>>>(hr, bsg + 2 * EMB, bsb + 2 * EMB);
    split_hl<<<(BATCH * 64 + 255) / 256, 256>>>(hr, hrA, BATCH * 64);
    gemm_bf16<EPI_SIG, false><<<gS, 256, SM_GEMM>>>(
        hrA, SA1, nullptr, nullptr, out + (size_t)2 * BATCH * N_ENTS, BATCH, N_ENTS);
}